// round 11
// baseline (speedup 1.0000x reference)
#include <cuda_runtime.h>
#include <cuda_fp16.h>
#include <cstdint>
#include <cstddef>

#define Mrows   16384
#define DMODEL  1024
#define FFDIM   4096
#define QKVN    3072
#define LAMBDA_INIT_F        0.35550906759096926f
#define ONE_MINUS_LAMBDA_F   0.64449093240903074f
#define QSCALE               0.17677669529663687f

// ---------------- scratch (device globals; no runtime allocs) ----------------
__device__ __align__(256) __half g_hbf   [(size_t)Mrows * DMODEL];
__device__ __align__(256) __half g_qkv   [(size_t)Mrows * QKVN];     // now fp16
__device__ __align__(256) __half g_attnbf[(size_t)Mrows * DMODEL];
__device__ __align__(256) float  g_conn  [(size_t)Mrows * DMODEL];
__device__ __align__(256) __half g_h2bf  [(size_t)Mrows * DMODEL];
__device__ __align__(256) __half g_ffnbf [(size_t)Mrows * FFDIM];
__device__ __align__(256) __half g_wqkv  [(size_t)QKVN   * DMODEL];
__device__ __align__(256) __half g_wo    [(size_t)DMODEL * DMODEL];
__device__ __align__(256) __half g_w1    [(size_t)FFDIM  * DMODEL];
__device__ __align__(256) __half g_w2    [(size_t)DMODEL * FFDIM];
__device__ float g_lambda;

// ---------------- PTX helpers (base sm_103 target; no 'a' features) ----------
__device__ __forceinline__ uint32_t smem_u32(const void* p) {
    uint32_t a;
    asm("{ .reg .u64 t; cvta.to.shared.u64 t, %1; cvt.u32.u64 %0, t; }" : "=r"(a) : "l"(p));
    return a;
}
__device__ __forceinline__ void cpasync16(uint32_t d, const void* g) {
    asm volatile("cp.async.cg.shared.global [%0], [%1], 16;" :: "r"(d), "l"(g));
}
#define CP_COMMIT()  asm volatile("cp.async.commit_group;" ::: "memory")
#define CP_WAIT2()   asm volatile("cp.async.wait_group 2;" ::: "memory")
#define CP_WAIT1()   asm volatile("cp.async.wait_group 1;" ::: "memory")
#define CP_WAIT0()   asm volatile("cp.async.wait_group 0;" ::: "memory")

#define LDMX4(r, addr) \
    asm volatile("ldmatrix.sync.aligned.m8n8.x4.shared.b16 {%0,%1,%2,%3}, [%4];" \
                 : "=r"((r)[0]), "=r"((r)[1]), "=r"((r)[2]), "=r"((r)[3]) : "r"(addr))

__device__ __forceinline__ void mma16816(float& c0, float& c1, float& c2, float& c3,
                                         uint32_t a0, uint32_t a1, uint32_t a2, uint32_t a3,
                                         uint32_t b0, uint32_t b1) {
    asm volatile(
        "mma.sync.aligned.m16n8k16.row.col.f32.f16.f16.f32 "
        "{%0,%1,%2,%3}, {%4,%5,%6,%7}, {%8,%9}, {%0,%1,%2,%3};"
        : "+f"(c0), "+f"(c1), "+f"(c2), "+f"(c3)
        : "r"(a0), "r"(a1), "r"(a2), "r"(a3), "r"(b0), "r"(b1));
}

// ---------------- lambda ----------------
__global__ void lambda_kernel(const float* __restrict__ lq1, const float* __restrict__ lq2,
                              const float* __restrict__ lk1, const float* __restrict__ lk2) {
    int l = threadIdx.x;
    float s1 = lq1[l] * lk1[l];
    float s2 = lq2[l] * lk2[l];
    #pragma unroll
    for (int o = 16; o; o >>= 1) {
        s1 += __shfl_xor_sync(0xffffffffu, s1, o);
        s2 += __shfl_xor_sync(0xffffffffu, s2, o);
    }
    if (l == 0) g_lambda = expf(s1) - expf(s2) + LAMBDA_INIT_F;
}

// ---------------- weight convert: fp32 [N,K] -> fp16 [N,K] -------------------
__global__ void convert_w_kernel(const float* __restrict__ src, __half* __restrict__ dst,
                                 int total) {
    int idx = blockIdx.x * 256 + threadIdx.x;
    if (idx >= total) return;
    dst[idx] = __float2half(src[idx]);
}

// ---------------- LayerNorm: fp32 in -> fp16 out ------------------------------
__global__ __launch_bounds__(256) void ln_kernel(const float* __restrict__ X,
                                                 const float* __restrict__ G,
                                                 const float* __restrict__ Bb,
                                                 __half* __restrict__ Y) {
    size_t row = blockIdx.x;
    int t = threadIdx.x;
    const float4 v = ((const float4*)(X + row * DMODEL))[t];
    float s  = v.x + v.y + v.z + v.w;
    float ss = v.x * v.x + v.y * v.y + v.z * v.z + v.w * v.w;
    #pragma unroll
    for (int o = 16; o; o >>= 1) {
        s  += __shfl_xor_sync(0xffffffffu, s,  o);
        ss += __shfl_xor_sync(0xffffffffu, ss, o);
    }
    __shared__ float sh_s[8], sh_ss[8];
    int w = t >> 5, l = t & 31;
    if (l == 0) { sh_s[w] = s; sh_ss[w] = ss; }
    __syncthreads();
    if (w == 0) {
        float a  = (l < 8) ? sh_s[l]  : 0.0f;
        float bq = (l < 8) ? sh_ss[l] : 0.0f;
        #pragma unroll
        for (int o = 4; o; o >>= 1) {
            a  += __shfl_xor_sync(0xffffffffu, a,  o);
            bq += __shfl_xor_sync(0xffffffffu, bq, o);
        }
        if (l == 0) { sh_s[0] = a; sh_ss[0] = bq; }
    }
    __syncthreads();
    float mu  = sh_s[0] * (1.0f / DMODEL);
    float var = sh_ss[0] * (1.0f / DMODEL) - mu * mu;
    float inv = rsqrtf(var + 1e-5f);
    const float4 gg = ((const float4*)G)[t];
    const float4 bb = ((const float4*)Bb)[t];
    float o0 = (v.x - mu) * inv * gg.x + bb.x;
    float o1 = (v.y - mu) * inv * gg.y + bb.y;
    float o2 = (v.z - mu) * inv * gg.z + bb.z;
    float o3 = (v.w - mu) * inv * gg.w + bb.w;
    __half* yr = Y + row * (size_t)DMODEL + t * 4;
    *(__half2*)(yr)     = __halves2half2(__float2half(o0), __float2half(o1));
    *(__half2*)(yr + 2) = __halves2half2(__float2half(o2), __float2half(o3));
}

// ---------------- per-token differential attention (fp16 in, fp16 out) -------
// QKV fused input: row pitch 3072, q at +0, k at +1024, v at +2048.
__global__ __launch_bounds__(64) void attn_kernel(const __half* __restrict__ QKV,
                                                  __half* __restrict__ O) {
    __shared__ float s_q[2][32][33];
    __shared__ float s_k[2][32][32];
    __shared__ float s_v[2][16][64];
    const int warp = threadIdx.x >> 5;
    const int lane = threadIdx.x & 31;
    const size_t t = (size_t)blockIdx.x * 2 + warp;
    const __half* q = QKV + t * QKVN;
    const __half* k = q + DMODEL;
    const __half* v = k + DMODEL;
    float (*qs)[33] = s_q[warp];
    float (*ks)[32] = s_k[warp];
    float (*vs)[64] = s_v[warp];

    // half2 loads: elements (idx, idx+1) share h and dd; j = 0 / 1.
    for (int idx = lane * 2; idx < DMODEL; idx += 64) {
        int h = idx >> 6, r = idx & 63;
        int dd = r >> 1;
        float2 qv = __half22float2(*(const __half2*)(q + idx));
        float2 kv = __half22float2(*(const __half2*)(k + idx));
        float2 vv = __half22float2(*(const __half2*)(v + idx));
        qs[h][dd]      = qv.x * QSCALE;
        qs[16 + h][dd] = qv.y * QSCALE;
        ks[h][dd]      = kv.x;
        ks[16 + h][dd] = kv.y;
        ((float*)vs)[idx]     = vv.x;
        ((float*)vs)[idx + 1] = vv.y;
    }
    __syncwarp();
    float qr[32];
    #pragma unroll
    for (int d = 0; d < 32; d++) qr[d] = qs[lane][d];
    float p[32];
    #pragma unroll
    for (int j = 0; j < 32; j++) {
        float s = 0.0f;
        #pragma unroll
        for (int d = 0; d < 32; d++) s += qr[d] * ks[j][d];
        p[j] = s;
    }
    float mx = p[0];
    #pragma unroll
    for (int j = 1; j < 32; j++) mx = fmaxf(mx, p[j]);
    float sum = 0.0f;
    #pragma unroll
    for (int j = 0; j < 32; j++) { p[j] = expf(p[j] - mx); sum += p[j]; }
    float rinv = 1.0f / sum;
    __syncwarp();
    #pragma unroll
    for (int j = 0; j < 32; j++) qs[lane][j] = p[j] * rinv;
    __syncwarp();

    const float lam = g_lambda;
    const int a = lane & 15;
    const int half = lane >> 4;
    float accv[32];
    #pragma unroll
    for (int e = 0; e < 32; e++) accv[e] = 0.0f;
    #pragma unroll
    for (int h = 0; h < 16; h++) {
        float w = qs[a][h] - lam * qs[16 + a][16 + h];
        const float* vrow = &vs[h][half * 32];
        #pragma unroll
        for (int e = 0; e < 32; e++) accv[e] += w * vrow[e];
    }
    float ss = 0.0f;
    #pragma unroll
    for (int e = 0; e < 32; e++) ss += accv[e] * accv[e];
    ss += __shfl_xor_sync(0xffffffffu, ss, 16);
    float scale = rsqrtf(ss * (1.0f / 64.0f) + 1e-5f) * ONE_MINUS_LAMBDA_F;

    __half* o = O + t * (size_t)DMODEL + a * 64 + half * 32;
    #pragma unroll
    for (int e = 0; e < 32; e += 2) {
        *(__half2*)(o + e) = __halves2half2(__float2half(accv[e] * scale),
                                            __float2half(accv[e + 1] * scale));
    }
}

// ---------------- HMMA GEMM, fp16, 2 CTAs/SM, 3-stage pipeline ---------------
// A:[M,Ko] fp16, W:[N,Ko] fp16. acc += A*W^T.
// 128x128 tile, warp tile 64x32 (8 warps 2m x 4n), BK=32.
// Stage: A,W each 128 x 80B = 20 KB; 3 stages = 60 KB -> 2 CTAs/SM.
// EPI: 1=bias 2=relu 4=+res(fp32) 8=fp16 out (else fp32 out)
#define PITCH  80u
#define TILE   10240u             // 128 * 80
#define OFF_A  0u
#define OFF_W  10240u
#define STG    20480u             // per stage
#define GSMEM  61440              // 3 stages

template <int EPI>
__global__ __launch_bounds__(256, 2)
void mma_gemm(const __half* __restrict__ A, const __half* __restrict__ W,
              const float* __restrict__ bias, const float* __restrict__ res,
              float* __restrict__ C, __half* __restrict__ Chl, int Nn, int Ko) {
    extern __shared__ __align__(1024) char smem[];
    const uint32_t sb = smem_u32(smem);
    const int tid = threadIdx.x;
    const int wid = tid >> 5, lane = tid & 31;
    const int m0 = blockIdx.y * 128, n0 = blockIdx.x * 128;
    const int wm = wid & 1, wn = wid >> 1;
    const int nk = Ko >> 5;            // BK = 32

    const __half* srcA = A + (size_t)m0 * Ko;
    const __half* srcW = W + (size_t)n0 * Ko;

    const int ldrow0 = tid >> 2;          // 0..63
    const int ldseg  = tid & 3;           // 0..3  (4 x 16B = 64B row)
    const uint32_t ldoff0 = (uint32_t)(ldrow0 * PITCH + ldseg * 16);

    const int lr = lane & 7, grp = lane >> 3;
    uint32_t aOff[4], bOff[2];
    #pragma unroll
    for (int mi = 0; mi < 4; mi++)
        aOff[mi] = (uint32_t)((wm * 64 + mi * 16 + lr + (grp & 1) * 8) * PITCH +
                              ((grp >> 1) * 8) * 2);
    #pragma unroll
    for (int nj = 0; nj < 2; nj++)
        bOff[nj] = (uint32_t)((wn * 32 + nj * 16 + lr + (grp >> 1) * 8) * PITCH +
                              ((grp & 1) * 8) * 2);

    float acc[4][4][4];
    #pragma unroll
    for (int i = 0; i < 4; i++)
        #pragma unroll
        for (int j = 0; j < 4; j++)
            #pragma unroll
            for (int e = 0; e < 4; e++) acc[i][j][e] = 0.0f;

    auto load_stage = [&](int kt, int buf) {
        uint32_t base = sb + (uint32_t)buf * STG;
        const __half* ap = srcA + kt * 32;
        const __half* wp = srcW + kt * 32;
        #pragma unroll
        for (int i = 0; i < 2; i++) {
            int row = ldrow0 + i * 64;
            uint32_t off = ldoff0 + (uint32_t)(i * 64 * PITCH);
            size_t roff = (size_t)row * Ko + ldseg * 8;
            cpasync16(base + OFF_A + off, ap + roff);
            cpasync16(base + OFF_W + off, wp + roff);
        }
        CP_COMMIT();
    };

    load_stage(0, 0);
    if (nk > 1) load_stage(1, 1);
    for (int kt = 0; kt < nk; kt++) {
        int buf = kt % 3;
        if (kt + 2 < nk) { load_stage(kt + 2, (kt + 2) % 3); CP_WAIT2(); }
        else if (kt + 1 < nk) { CP_WAIT1(); }
        else { CP_WAIT0(); }
        __syncthreads();
        uint32_t base = sb + (uint32_t)buf * STG;
        #pragma unroll
        for (int ks = 0; ks < 2; ks++) {
            uint32_t af[4][4];
            #pragma unroll
            for (int mi = 0; mi < 4; mi++)
                LDMX4(af[mi], base + OFF_A + aOff[mi] + ks * 32);
            uint32_t bf[4][2];
            #pragma unroll
            for (int nj = 0; nj < 2; nj++) {
                uint32_t th[4];
                LDMX4(th, base + OFF_W + bOff[nj] + ks * 32);
                bf[2 * nj][0] = th[0];     bf[2 * nj][1] = th[1];
                bf[2 * nj + 1][0] = th[2]; bf[2 * nj + 1][1] = th[3];
            }
            #pragma unroll
            for (int mi = 0; mi < 4; mi++)
                #pragma unroll
                for (int ni = 0; ni < 4; ni++)
                    mma16816(acc[mi][ni][0], acc[mi][ni][1], acc[mi][ni][2], acc[mi][ni][3],
                             af[mi][0], af[mi][1], af[mi][2], af[mi][3],
                             bf[ni][0], bf[ni][1]);
        }
        __syncthreads();
    }

    // epilogue
    const int gm = m0 + wm * 64;
    const int gn = n0 + wn * 32;
    const int rr = lane >> 2;
    const int cc = (lane & 3) * 2;
    #pragma unroll
    for (int mi = 0; mi < 4; mi++) {
        #pragma unroll
        for (int ni = 0; ni < 4; ni++) {
            int col = gn + ni * 8 + cc;
            float2 bv = make_float2(0.f, 0.f);
            if (EPI & 1) bv = *(const float2*)(bias + col);
            #pragma unroll
            for (int hh = 0; hh < 2; hh++) {
                int row = gm + mi * 16 + rr + hh * 8;
                float v0 = acc[mi][ni][2 * hh];
                float v1 = acc[mi][ni][2 * hh + 1];
                if (EPI & 1) { v0 += bv.x; v1 += bv.y; }
                if (EPI & 2) { v0 = fmaxf(v0, 0.0f); v1 = fmaxf(v1, 0.0f); }
                if (EPI & 4) {
                    float2 r2 = *(const float2*)(res + (size_t)row * Nn + col);
                    v0 += r2.x; v1 += r2.y;
                }
                if (EPI & 8) {
                    *(__half2*)(Chl + (size_t)row * Nn + col) =
                        __halves2half2(__float2half(v0), __float2half(v1));
                } else {
                    *(float2*)(C + (size_t)row * Nn + col) = make_float2(v0, v1);
                }
            }
        }
    }
}

// ---------------- launch ----------------
extern "C" void kernel_launch(void* const* d_in, const int* in_sizes, int n_in,
                              void* d_out, int out_size) {
    const float* x    = (const float*)d_in[0];
    const float* Wq   = (const float*)d_in[1];
    const float* Wk   = (const float*)d_in[2];
    const float* Wv   = (const float*)d_in[3];
    const float* lq1  = (const float*)d_in[4];
    const float* lq2  = (const float*)d_in[5];
    const float* lk1  = (const float*)d_in[6];
    const float* lk2  = (const float*)d_in[7];
    const float* Wo   = (const float*)d_in[8];
    const float* bo   = (const float*)d_in[9];
    const float* ln1g = (const float*)d_in[10];
    const float* ln1b = (const float*)d_in[11];
    const float* ln2g = (const float*)d_in[12];
    const float* ln2b = (const float*)d_in[13];
    const float* W1   = (const float*)d_in[14];
    const float* b1   = (const float*)d_in[15];
    const float* W2   = (const float*)d_in[16];
    const float* b2   = (const float*)d_in[17];
    float* out = (float*)d_out;

    __half *phbf, *pqkv, *pattnbf, *ph2bf, *pffnbf, *pwqkv, *pwo, *pw1, *pw2;
    float *pconn;
    cudaGetSymbolAddress((void**)&phbf,    g_hbf);
    cudaGetSymbolAddress((void**)&pqkv,    g_qkv);
    cudaGetSymbolAddress((void**)&pattnbf, g_attnbf);
    cudaGetSymbolAddress((void**)&pconn,   g_conn);
    cudaGetSymbolAddress((void**)&ph2bf,   g_h2bf);
    cudaGetSymbolAddress((void**)&pffnbf,  g_ffnbf);
    cudaGetSymbolAddress((void**)&pwqkv,   g_wqkv);
    cudaGetSymbolAddress((void**)&pwo,     g_wo);
    cudaGetSymbolAddress((void**)&pw1,     g_w1);
    cudaGetSymbolAddress((void**)&pw2,     g_w2);

    cudaFuncSetAttribute(mma_gemm<8>,  cudaFuncAttributeMaxDynamicSharedMemorySize, GSMEM);
    cudaFuncSetAttribute(mma_gemm<5>,  cudaFuncAttributeMaxDynamicSharedMemorySize, GSMEM);
    cudaFuncSetAttribute(mma_gemm<11>, cudaFuncAttributeMaxDynamicSharedMemorySize, GSMEM);

    lambda_kernel<<<1, 32>>>(lq1, lq2, lk1, lk2);

    // weight converts (fp32 -> fp16); Q,K,V stacked into one [3072, 1024]
    int tw = DMODEL * DMODEL;
    convert_w_kernel<<<tw / 256, 256>>>(Wq, pwqkv,                               tw);
    convert_w_kernel<<<tw / 256, 256>>>(Wk, pwqkv + (size_t)DMODEL * DMODEL,     tw);
    convert_w_kernel<<<tw / 256, 256>>>(Wv, pwqkv + (size_t)2 * DMODEL * DMODEL, tw);
    convert_w_kernel<<<tw / 256, 256>>>(Wo, pwo, tw);
    int t1 = FFDIM * DMODEL;
    convert_w_kernel<<<t1 / 256, 256>>>(W1, pw1, t1);
    convert_w_kernel<<<t1 / 256, 256>>>(W2, pw2, t1);

    // LN1: x -> hbf
    ln_kernel<<<Mrows, 256>>>(x, ln1g, ln1b, phbf);

    // fused QKV: [M,1024] x [3072,1024]^T -> [M,3072] fp16
    dim3 gqkv(QKVN / 128, Mrows / 128);   // (24,128)
    mma_gemm<8><<<gqkv, 256, GSMEM>>>(phbf, pwqkv, nullptr, nullptr, nullptr, pqkv, QKVN, DMODEL);

    attn_kernel<<<Mrows / 2, 64>>>(pqkv, pattnbf);

    // conn = x + attn @ Wo^T + bo
    dim3 gq(DMODEL / 128, Mrows / 128);   // (8,128)
    mma_gemm<5><<<gq, 256, GSMEM>>>(pattnbf, pwo, bo, x, pconn, nullptr, DMODEL, DMODEL);

    // LN2: conn -> h2bf
    ln_kernel<<<Mrows, 256>>>(pconn, ln2g, ln2b, ph2bf);

    // ffn = relu(h2 @ W1^T + b1) -> fp16
    dim3 g1(FFDIM / 128, Mrows / 128);    // (32,128)
    mma_gemm<11><<<g1, 256, GSMEM>>>(ph2bf, pw1, b1, nullptr, nullptr, pffnbf, FFDIM, DMODEL);

    // out = conn + ffn @ W2^T + b2
    mma_gemm<5><<<gq, 256, GSMEM>>>(pffnbf, pw2, b2, pconn, out, nullptr, DMODEL, FFDIM);
}

// round 12
// speedup vs baseline: 1.2291x; 1.2291x over previous
#include <cuda_runtime.h>
#include <cuda_fp16.h>
#include <cstdint>
#include <cstddef>

#define Mrows   16384
#define DMODEL  1024
#define FFDIM   4096
#define QKVN    3072
#define LAMBDA_INIT_F        0.35550906759096926f
#define ONE_MINUS_LAMBDA_F   0.64449093240903074f
#define QSCALE               0.17677669529663687f

// ---------------- scratch (device globals; no runtime allocs) ----------------
__device__ __align__(256) __half g_hbf   [(size_t)Mrows * DMODEL];
__device__ __align__(256) __half g_qkv   [(size_t)Mrows * QKVN];
__device__ __align__(256) __half g_attnbf[(size_t)Mrows * DMODEL];
__device__ __align__(256) float  g_conn  [(size_t)Mrows * DMODEL];
__device__ __align__(256) __half g_h2bf  [(size_t)Mrows * DMODEL];
__device__ __align__(256) __half g_ffnbf [(size_t)Mrows * FFDIM];
__device__ __align__(256) __half g_wqkv  [(size_t)QKVN   * DMODEL];
__device__ __align__(256) __half g_wo    [(size_t)DMODEL * DMODEL];
__device__ __align__(256) __half g_w1    [(size_t)FFDIM  * DMODEL];
__device__ __align__(256) __half g_w2    [(size_t)DMODEL * FFDIM];
__device__ float g_lambda;

// ---------------- PTX helpers (base sm_103 target; no 'a' features) ----------
__device__ __forceinline__ uint32_t smem_u32(const void* p) {
    uint32_t a;
    asm("{ .reg .u64 t; cvta.to.shared.u64 t, %1; cvt.u32.u64 %0, t; }" : "=r"(a) : "l"(p));
    return a;
}
__device__ __forceinline__ void cpasync16(uint32_t d, const void* g) {
    asm volatile("cp.async.cg.shared.global [%0], [%1], 16;" :: "r"(d), "l"(g));
}
#define CP_COMMIT()  asm volatile("cp.async.commit_group;" ::: "memory")
#define CP_WAIT1()   asm volatile("cp.async.wait_group 1;" ::: "memory")
#define CP_WAIT0()   asm volatile("cp.async.wait_group 0;" ::: "memory")

#define LDMX4(r, addr) \
    asm volatile("ldmatrix.sync.aligned.m8n8.x4.shared.b16 {%0,%1,%2,%3}, [%4];" \
                 : "=r"((r)[0]), "=r"((r)[1]), "=r"((r)[2]), "=r"((r)[3]) : "r"(addr))

__device__ __forceinline__ void mma16816(float& c0, float& c1, float& c2, float& c3,
                                         uint32_t a0, uint32_t a1, uint32_t a2, uint32_t a3,
                                         uint32_t b0, uint32_t b1) {
    asm volatile(
        "mma.sync.aligned.m16n8k16.row.col.f32.f16.f16.f32 "
        "{%0,%1,%2,%3}, {%4,%5,%6,%7}, {%8,%9}, {%0,%1,%2,%3};"
        : "+f"(c0), "+f"(c1), "+f"(c2), "+f"(c3)
        : "r"(a0), "r"(a1), "r"(a2), "r"(a3), "r"(b0), "r"(b1));
}

// ---------------- lambda ----------------
__global__ void lambda_kernel(const float* __restrict__ lq1, const float* __restrict__ lq2,
                              const float* __restrict__ lk1, const float* __restrict__ lk2) {
    int l = threadIdx.x;
    float s1 = lq1[l] * lk1[l];
    float s2 = lq2[l] * lk2[l];
    #pragma unroll
    for (int o = 16; o; o >>= 1) {
        s1 += __shfl_xor_sync(0xffffffffu, s1, o);
        s2 += __shfl_xor_sync(0xffffffffu, s2, o);
    }
    if (l == 0) g_lambda = expf(s1) - expf(s2) + LAMBDA_INIT_F;
}

// ---------------- fused weight convert: all six fp32 -> fp16 -----------------
#define WSEG 1048576u   // DMODEL*DMODEL
__global__ void convert_all(const float* __restrict__ Wq, const float* __restrict__ Wk,
                            const float* __restrict__ Wv, const float* __restrict__ Wo,
                            const float* __restrict__ W1, const float* __restrict__ W2,
                            __half* __restrict__ dqkv, __half* __restrict__ dwo,
                            __half* __restrict__ dw1, __half* __restrict__ dw2) {
    uint32_t idx = blockIdx.x * 256u + threadIdx.x;   // total 12*WSEG
    if (idx < WSEG)            dqkv[idx] = __float2half(Wq[idx]);
    else if (idx < 2 * WSEG)   dqkv[idx] = __float2half(Wk[idx - WSEG]);
    else if (idx < 3 * WSEG)   dqkv[idx] = __float2half(Wv[idx - 2 * WSEG]);
    else if (idx < 4 * WSEG)   dwo[idx - 3 * WSEG] = __float2half(Wo[idx - 3 * WSEG]);
    else if (idx < 8 * WSEG)   dw1[idx - 4 * WSEG] = __float2half(W1[idx - 4 * WSEG]);
    else                       dw2[idx - 8 * WSEG] = __float2half(W2[idx - 8 * WSEG]);
}

// ---------------- LayerNorm: fp32 in -> fp16 out ------------------------------
__global__ __launch_bounds__(256) void ln_kernel(const float* __restrict__ X,
                                                 const float* __restrict__ G,
                                                 const float* __restrict__ Bb,
                                                 __half* __restrict__ Y) {
    size_t row = blockIdx.x;
    int t = threadIdx.x;
    const float4 v = ((const float4*)(X + row * DMODEL))[t];
    float s  = v.x + v.y + v.z + v.w;
    float ss = v.x * v.x + v.y * v.y + v.z * v.z + v.w * v.w;
    #pragma unroll
    for (int o = 16; o; o >>= 1) {
        s  += __shfl_xor_sync(0xffffffffu, s,  o);
        ss += __shfl_xor_sync(0xffffffffu, ss, o);
    }
    __shared__ float sh_s[8], sh_ss[8];
    int w = t >> 5, l = t & 31;
    if (l == 0) { sh_s[w] = s; sh_ss[w] = ss; }
    __syncthreads();
    if (w == 0) {
        float a  = (l < 8) ? sh_s[l]  : 0.0f;
        float bq = (l < 8) ? sh_ss[l] : 0.0f;
        #pragma unroll
        for (int o = 4; o; o >>= 1) {
            a  += __shfl_xor_sync(0xffffffffu, a,  o);
            bq += __shfl_xor_sync(0xffffffffu, bq, o);
        }
        if (l == 0) { sh_s[0] = a; sh_ss[0] = bq; }
    }
    __syncthreads();
    float mu  = sh_s[0] * (1.0f / DMODEL);
    float var = sh_ss[0] * (1.0f / DMODEL) - mu * mu;
    float inv = rsqrtf(var + 1e-5f);
    const float4 gg = ((const float4*)G)[t];
    const float4 bb = ((const float4*)Bb)[t];
    float o0 = (v.x - mu) * inv * gg.x + bb.x;
    float o1 = (v.y - mu) * inv * gg.y + bb.y;
    float o2 = (v.z - mu) * inv * gg.z + bb.z;
    float o3 = (v.w - mu) * inv * gg.w + bb.w;
    __half* yr = Y + row * (size_t)DMODEL + t * 4;
    *(__half2*)(yr)     = __halves2half2(__float2half(o0), __float2half(o1));
    *(__half2*)(yr + 2) = __halves2half2(__float2half(o2), __float2half(o3));
}

// ---------------- per-token differential attention (fp16 in, fp16 out) -------
// QKV fused input: row pitch 3072, q at +0, k at +1024, v at +2048.
__global__ __launch_bounds__(64) void attn_kernel(const __half* __restrict__ QKV,
                                                  __half* __restrict__ O) {
    __shared__ float s_q[2][32][33];
    __shared__ float s_k[2][32][32];
    __shared__ float s_v[2][16][64];
    const int warp = threadIdx.x >> 5;
    const int lane = threadIdx.x & 31;
    const size_t t = (size_t)blockIdx.x * 2 + warp;
    const __half* q = QKV + t * QKVN;
    const __half* k = q + DMODEL;
    const __half* v = k + DMODEL;
    float (*qs)[33] = s_q[warp];
    float (*ks)[32] = s_k[warp];
    float (*vs)[64] = s_v[warp];

    for (int idx = lane * 2; idx < DMODEL; idx += 64) {
        int h = idx >> 6, r = idx & 63;
        int dd = r >> 1;
        float2 qv = __half22float2(*(const __half2*)(q + idx));
        float2 kv = __half22float2(*(const __half2*)(k + idx));
        float2 vv = __half22float2(*(const __half2*)(v + idx));
        qs[h][dd]      = qv.x * QSCALE;
        qs[16 + h][dd] = qv.y * QSCALE;
        ks[h][dd]      = kv.x;
        ks[16 + h][dd] = kv.y;
        ((float*)vs)[idx]     = vv.x;
        ((float*)vs)[idx + 1] = vv.y;
    }
    __syncwarp();
    float qr[32];
    #pragma unroll
    for (int d = 0; d < 32; d++) qr[d] = qs[lane][d];
    float p[32];
    #pragma unroll
    for (int j = 0; j < 32; j++) {
        float s = 0.0f;
        #pragma unroll
        for (int d = 0; d < 32; d++) s += qr[d] * ks[j][d];
        p[j] = s;
    }
    float mx = p[0];
    #pragma unroll
    for (int j = 1; j < 32; j++) mx = fmaxf(mx, p[j]);
    float sum = 0.0f;
    #pragma unroll
    for (int j = 0; j < 32; j++) { p[j] = expf(p[j] - mx); sum += p[j]; }
    float rinv = 1.0f / sum;
    __syncwarp();
    #pragma unroll
    for (int j = 0; j < 32; j++) qs[lane][j] = p[j] * rinv;
    __syncwarp();

    const float lam = g_lambda;
    const int a = lane & 15;
    const int half = lane >> 4;
    float accv[32];
    #pragma unroll
    for (int e = 0; e < 32; e++) accv[e] = 0.0f;
    #pragma unroll
    for (int h = 0; h < 16; h++) {
        float w = qs[a][h] - lam * qs[16 + a][16 + h];
        const float* vrow = &vs[h][half * 32];
        #pragma unroll
        for (int e = 0; e < 32; e++) accv[e] += w * vrow[e];
    }
    float ss = 0.0f;
    #pragma unroll
    for (int e = 0; e < 32; e++) ss += accv[e] * accv[e];
    ss += __shfl_xor_sync(0xffffffffu, ss, 16);
    float scale = rsqrtf(ss * (1.0f / 64.0f) + 1e-5f) * ONE_MINUS_LAMBDA_F;

    __half* o = O + t * (size_t)DMODEL + a * 64 + half * 32;
    #pragma unroll
    for (int e = 0; e < 32; e += 2) {
        *(__half2*)(o + e) = __halves2half2(__float2half(accv[e] * scale),
                                            __float2half(accv[e + 1] * scale));
    }
}

// ---------------- HMMA GEMM, fp16, 4 warps, warp tile 64x64, 2 CTAs/SM -------
// A:[M,Ko] fp16, W:[N,Ko] fp16. acc += A*W^T.
// 128x128 CTA tile, 4 warps (2m x 2n, each 64x64), BK=32, double-buffered.
// Per ks: 8 LDSM.x4 : 32 HMMA (density 4.0).
// Stage: A,W each 128 x 80B = 20 KB; 2 stages = 40 KB -> 2 CTAs/SM.
// EPI: 1=bias 2=relu 4=+res(fp32) 8=fp16 out (else fp32 out)
#define PITCH  80u
#define TILE   10240u             // 128 * 80
#define OFF_A  0u
#define OFF_W  10240u
#define STG    20480u             // per stage
#define GSMEM  40960              // 2 stages

template <int EPI>
__global__ __launch_bounds__(128, 2)
void mma_gemm(const __half* __restrict__ A, const __half* __restrict__ W,
              const float* __restrict__ bias, const float* __restrict__ res,
              float* __restrict__ C, __half* __restrict__ Chl, int Nn, int Ko) {
    extern __shared__ __align__(1024) char smem[];
    const uint32_t sb = smem_u32(smem);
    const int tid = threadIdx.x;
    const int wid = tid >> 5, lane = tid & 31;
    const int m0 = blockIdx.y * 128, n0 = blockIdx.x * 128;
    const int wm = wid & 1, wn = wid >> 1;
    const int nk = Ko >> 5;            // BK = 32

    const __half* srcA = A + (size_t)m0 * Ko;
    const __half* srcW = W + (size_t)n0 * Ko;

    // cp.async mapping: 128 thr -> 32 rows x 4 segs (16B); 4 row-iters/tile
    const int ldrow0 = tid >> 2;          // 0..31
    const int ldseg  = tid & 3;           // 0..3  (4 x 16B = 64B payload/row)
    const uint32_t ldoff0 = (uint32_t)(ldrow0 * PITCH + ldseg * 16);

    // ldmatrix per-lane offsets (within a tile)
    const int lr = lane & 7, grp = lane >> 3;
    uint32_t aOff[4], bOff[4];
    #pragma unroll
    for (int mi = 0; mi < 4; mi++)
        aOff[mi] = (uint32_t)((wm * 64 + mi * 16 + lr + (grp & 1) * 8) * PITCH +
                              ((grp >> 1) * 8) * 2);
    #pragma unroll
    for (int nj = 0; nj < 4; nj++)
        bOff[nj] = (uint32_t)((wn * 64 + nj * 16 + lr + (grp >> 1) * 8) * PITCH +
                              ((grp & 1) * 8) * 2);

    float acc[4][8][4];
    #pragma unroll
    for (int i = 0; i < 4; i++)
        #pragma unroll
        for (int j = 0; j < 8; j++)
            #pragma unroll
            for (int e = 0; e < 4; e++) acc[i][j][e] = 0.0f;

    auto load_stage = [&](int kt, int buf) {
        uint32_t base = sb + (uint32_t)buf * STG;
        const __half* ap = srcA + kt * 32;
        const __half* wp = srcW + kt * 32;
        #pragma unroll
        for (int i = 0; i < 4; i++) {
            int row = ldrow0 + i * 32;
            uint32_t off = ldoff0 + (uint32_t)(i * 32 * PITCH);
            size_t roff = (size_t)row * Ko + ldseg * 8;
            cpasync16(base + OFF_A + off, ap + roff);
            cpasync16(base + OFF_W + off, wp + roff);
        }
        CP_COMMIT();
    };

    load_stage(0, 0);
    for (int kt = 0; kt < nk; kt++) {
        int buf = kt & 1;
        if (kt + 1 < nk) { load_stage(kt + 1, buf ^ 1); CP_WAIT1(); }
        else             { CP_WAIT0(); }
        __syncthreads();
        uint32_t base = sb + (uint32_t)buf * STG;
        #pragma unroll
        for (int ks = 0; ks < 2; ks++) {
            uint32_t af[4][4];
            #pragma unroll
            for (int mi = 0; mi < 4; mi++)
                LDMX4(af[mi], base + OFF_A + aOff[mi] + ks * 32);
            uint32_t bf[8][2];
            #pragma unroll
            for (int nj = 0; nj < 4; nj++) {
                uint32_t th[4];
                LDMX4(th, base + OFF_W + bOff[nj] + ks * 32);
                bf[2 * nj][0] = th[0];     bf[2 * nj][1] = th[1];
                bf[2 * nj + 1][0] = th[2]; bf[2 * nj + 1][1] = th[3];
            }
            #pragma unroll
            for (int mi = 0; mi < 4; mi++)
                #pragma unroll
                for (int ni = 0; ni < 8; ni++)
                    mma16816(acc[mi][ni][0], acc[mi][ni][1], acc[mi][ni][2], acc[mi][ni][3],
                             af[mi][0], af[mi][1], af[mi][2], af[mi][3],
                             bf[ni][0], bf[ni][1]);
        }
        __syncthreads();
    }

    // epilogue
    const int gm = m0 + wm * 64;
    const int gn = n0 + wn * 64;
    const int rr = lane >> 2;
    const int cc = (lane & 3) * 2;
    #pragma unroll
    for (int mi = 0; mi < 4; mi++) {
        #pragma unroll
        for (int ni = 0; ni < 8; ni++) {
            int col = gn + ni * 8 + cc;
            float2 bv = make_float2(0.f, 0.f);
            if (EPI & 1) bv = *(const float2*)(bias + col);
            #pragma unroll
            for (int hh = 0; hh < 2; hh++) {
                int row = gm + mi * 16 + rr + hh * 8;
                float v0 = acc[mi][ni][2 * hh];
                float v1 = acc[mi][ni][2 * hh + 1];
                if (EPI & 1) { v0 += bv.x; v1 += bv.y; }
                if (EPI & 2) { v0 = fmaxf(v0, 0.0f); v1 = fmaxf(v1, 0.0f); }
                if (EPI & 4) {
                    float2 r2 = *(const float2*)(res + (size_t)row * Nn + col);
                    v0 += r2.x; v1 += r2.y;
                }
                if (EPI & 8) {
                    *(__half2*)(Chl + (size_t)row * Nn + col) =
                        __halves2half2(__float2half(v0), __float2half(v1));
                } else {
                    *(float2*)(C + (size_t)row * Nn + col) = make_float2(v0, v1);
                }
            }
        }
    }
}

// ---------------- launch ----------------
extern "C" void kernel_launch(void* const* d_in, const int* in_sizes, int n_in,
                              void* d_out, int out_size) {
    const float* x    = (const float*)d_in[0];
    const float* Wq   = (const float*)d_in[1];
    const float* Wk   = (const float*)d_in[2];
    const float* Wv   = (const float*)d_in[3];
    const float* lq1  = (const float*)d_in[4];
    const float* lq2  = (const float*)d_in[5];
    const float* lk1  = (const float*)d_in[6];
    const float* lk2  = (const float*)d_in[7];
    const float* Wo   = (const float*)d_in[8];
    const float* bo   = (const float*)d_in[9];
    const float* ln1g = (const float*)d_in[10];
    const float* ln1b = (const float*)d_in[11];
    const float* ln2g = (const float*)d_in[12];
    const float* ln2b = (const float*)d_in[13];
    const float* W1   = (const float*)d_in[14];
    const float* b1   = (const float*)d_in[15];
    const float* W2   = (const float*)d_in[16];
    const float* b2   = (const float*)d_in[17];
    float* out = (float*)d_out;

    __half *phbf, *pqkv, *pattnbf, *ph2bf, *pffnbf, *pwqkv, *pwo, *pw1, *pw2;
    float *pconn;
    cudaGetSymbolAddress((void**)&phbf,    g_hbf);
    cudaGetSymbolAddress((void**)&pqkv,    g_qkv);
    cudaGetSymbolAddress((void**)&pattnbf, g_attnbf);
    cudaGetSymbolAddress((void**)&pconn,   g_conn);
    cudaGetSymbolAddress((void**)&ph2bf,   g_h2bf);
    cudaGetSymbolAddress((void**)&pffnbf,  g_ffnbf);
    cudaGetSymbolAddress((void**)&pwqkv,   g_wqkv);
    cudaGetSymbolAddress((void**)&pwo,     g_wo);
    cudaGetSymbolAddress((void**)&pw1,     g_w1);
    cudaGetSymbolAddress((void**)&pw2,     g_w2);

    cudaFuncSetAttribute(mma_gemm<8>,  cudaFuncAttributeMaxDynamicSharedMemorySize, GSMEM);
    cudaFuncSetAttribute(mma_gemm<5>,  cudaFuncAttributeMaxDynamicSharedMemorySize, GSMEM);
    cudaFuncSetAttribute(mma_gemm<11>, cudaFuncAttributeMaxDynamicSharedMemorySize, GSMEM);

    lambda_kernel<<<1, 32>>>(lq1, lq2, lk1, lk2);

    // fused weight convert (12M elements)
    convert_all<<<(12 * WSEG) / 256, 256>>>(Wq, Wk, Wv, Wo, W1, W2,
                                            pwqkv, pwo, pw1, pw2);

    // LN1: x -> hbf
    ln_kernel<<<Mrows, 256>>>(x, ln1g, ln1b, phbf);

    // fused QKV: [M,1024] x [3072,1024]^T -> [M,3072] fp16
    dim3 gqkv(QKVN / 128, Mrows / 128);   // (24,128)
    mma_gemm<8><<<gqkv, 128, GSMEM>>>(phbf, pwqkv, nullptr, nullptr, nullptr, pqkv, QKVN, DMODEL);

    attn_kernel<<<Mrows / 2, 64>>>(pqkv, pattnbf);

    // conn = x + attn @ Wo^T + bo
    dim3 gq(DMODEL / 128, Mrows / 128);   // (8,128)
    mma_gemm<5><<<gq, 128, GSMEM>>>(pattnbf, pwo, bo, x, pconn, nullptr, DMODEL, DMODEL);

    // LN2: conn -> h2bf
    ln_kernel<<<Mrows, 256>>>(pconn, ln2g, ln2b, ph2bf);

    // ffn = relu(h2 @ W1^T + b1) -> fp16
    dim3 g1(FFDIM / 128, Mrows / 128);    // (32,128)
    mma_gemm<11><<<g1, 128, GSMEM>>>(ph2bf, pw1, b1, nullptr, nullptr, pffnbf, FFDIM, DMODEL);

    // out = conn + ffn @ W2^T + b2
    mma_gemm<5><<<gq, 128, GSMEM>>>(pffnbf, pw2, b2, pconn, out, nullptr, DMODEL, FFDIM);
}

// round 13
// speedup vs baseline: 1.2508x; 1.0176x over previous
#include <cuda_runtime.h>
#include <cuda_fp16.h>
#include <cstdint>
#include <cstddef>

#define Mrows   16384
#define DMODEL  1024
#define FFDIM   4096
#define QKVN    3072
#define LAMBDA_INIT_F        0.35550906759096926f
#define ONE_MINUS_LAMBDA_F   0.64449093240903074f
#define QSCALE               0.17677669529663687f

// ---------------- scratch (device globals; no runtime allocs) ----------------
__device__ __align__(256) __half g_hbf   [(size_t)Mrows * DMODEL];
__device__ __align__(256) __half g_qkv   [(size_t)Mrows * QKVN];
__device__ __align__(256) __half g_attnbf[(size_t)Mrows * DMODEL];
__device__ __align__(256) float  g_conn  [(size_t)Mrows * DMODEL];
__device__ __align__(256) __half g_h2bf  [(size_t)Mrows * DMODEL];
__device__ __align__(256) __half g_ffnbf [(size_t)Mrows * FFDIM];
__device__ __align__(256) __half g_wqkv  [(size_t)QKVN   * DMODEL];
__device__ __align__(256) __half g_wo    [(size_t)DMODEL * DMODEL];
__device__ __align__(256) __half g_w1    [(size_t)FFDIM  * DMODEL];
__device__ __align__(256) __half g_w2    [(size_t)DMODEL * FFDIM];
__device__ float g_lambda;

// ---------------- PTX helpers (base sm_103 target; no 'a' features) ----------
__device__ __forceinline__ uint32_t smem_u32(const void* p) {
    uint32_t a;
    asm("{ .reg .u64 t; cvta.to.shared.u64 t, %1; cvt.u32.u64 %0, t; }" : "=r"(a) : "l"(p));
    return a;
}
__device__ __forceinline__ void cpasync16(uint32_t d, const void* g) {
    asm volatile("cp.async.cg.shared.global [%0], [%1], 16;" :: "r"(d), "l"(g));
}
#define CP_COMMIT()  asm volatile("cp.async.commit_group;" ::: "memory")
#define CP_WAIT2()   asm volatile("cp.async.wait_group 2;" ::: "memory")
#define CP_WAIT1()   asm volatile("cp.async.wait_group 1;" ::: "memory")
#define CP_WAIT0()   asm volatile("cp.async.wait_group 0;" ::: "memory")

#define LDMX4(r, addr) \
    asm volatile("ldmatrix.sync.aligned.m8n8.x4.shared.b16 {%0,%1,%2,%3}, [%4];" \
                 : "=r"((r)[0]), "=r"((r)[1]), "=r"((r)[2]), "=r"((r)[3]) : "r"(addr))

__device__ __forceinline__ void mma16816(float& c0, float& c1, float& c2, float& c3,
                                         uint32_t a0, uint32_t a1, uint32_t a2, uint32_t a3,
                                         uint32_t b0, uint32_t b1) {
    asm volatile(
        "mma.sync.aligned.m16n8k16.row.col.f32.f16.f16.f32 "
        "{%0,%1,%2,%3}, {%4,%5,%6,%7}, {%8,%9}, {%0,%1,%2,%3};"
        : "+f"(c0), "+f"(c1), "+f"(c2), "+f"(c3)
        : "r"(a0), "r"(a1), "r"(a2), "r"(a3), "r"(b0), "r"(b1));
}

// ---------------- lambda ----------------
__global__ void lambda_kernel(const float* __restrict__ lq1, const float* __restrict__ lq2,
                              const float* __restrict__ lk1, const float* __restrict__ lk2) {
    int l = threadIdx.x;
    float s1 = lq1[l] * lk1[l];
    float s2 = lq2[l] * lk2[l];
    #pragma unroll
    for (int o = 16; o; o >>= 1) {
        s1 += __shfl_xor_sync(0xffffffffu, s1, o);
        s2 += __shfl_xor_sync(0xffffffffu, s2, o);
    }
    if (l == 0) g_lambda = expf(s1) - expf(s2) + LAMBDA_INIT_F;
}

// ---------------- fused weight convert: all six fp32 -> fp16 -----------------
#define WSEG 1048576u   // DMODEL*DMODEL
__global__ void convert_all(const float* __restrict__ Wq, const float* __restrict__ Wk,
                            const float* __restrict__ Wv, const float* __restrict__ Wo,
                            const float* __restrict__ W1, const float* __restrict__ W2,
                            __half* __restrict__ dqkv, __half* __restrict__ dwo,
                            __half* __restrict__ dw1, __half* __restrict__ dw2) {
    uint32_t idx = blockIdx.x * 256u + threadIdx.x;   // total 12*WSEG
    if (idx < WSEG)            dqkv[idx] = __float2half(Wq[idx]);
    else if (idx < 2 * WSEG)   dqkv[idx] = __float2half(Wk[idx - WSEG]);
    else if (idx < 3 * WSEG)   dqkv[idx] = __float2half(Wv[idx - 2 * WSEG]);
    else if (idx < 4 * WSEG)   dwo[idx - 3 * WSEG] = __float2half(Wo[idx - 3 * WSEG]);
    else if (idx < 8 * WSEG)   dw1[idx - 4 * WSEG] = __float2half(W1[idx - 4 * WSEG]);
    else                       dw2[idx - 8 * WSEG] = __float2half(W2[idx - 8 * WSEG]);
}

// ---------------- LayerNorm: fp32 in -> fp16 out ------------------------------
__global__ __launch_bounds__(256) void ln_kernel(const float* __restrict__ X,
                                                 const float* __restrict__ G,
                                                 const float* __restrict__ Bb,
                                                 __half* __restrict__ Y) {
    size_t row = blockIdx.x;
    int t = threadIdx.x;
    const float4 v = ((const float4*)(X + row * DMODEL))[t];
    float s  = v.x + v.y + v.z + v.w;
    float ss = v.x * v.x + v.y * v.y + v.z * v.z + v.w * v.w;
    #pragma unroll
    for (int o = 16; o; o >>= 1) {
        s  += __shfl_xor_sync(0xffffffffu, s,  o);
        ss += __shfl_xor_sync(0xffffffffu, ss, o);
    }
    __shared__ float sh_s[8], sh_ss[8];
    int w = t >> 5, l = t & 31;
    if (l == 0) { sh_s[w] = s; sh_ss[w] = ss; }
    __syncthreads();
    if (w == 0) {
        float a  = (l < 8) ? sh_s[l]  : 0.0f;
        float bq = (l < 8) ? sh_ss[l] : 0.0f;
        #pragma unroll
        for (int o = 4; o; o >>= 1) {
            a  += __shfl_xor_sync(0xffffffffu, a,  o);
            bq += __shfl_xor_sync(0xffffffffu, bq, o);
        }
        if (l == 0) { sh_s[0] = a; sh_ss[0] = bq; }
    }
    __syncthreads();
    float mu  = sh_s[0] * (1.0f / DMODEL);
    float var = sh_ss[0] * (1.0f / DMODEL) - mu * mu;
    float inv = rsqrtf(var + 1e-5f);
    const float4 gg = ((const float4*)G)[t];
    const float4 bb = ((const float4*)Bb)[t];
    float o0 = (v.x - mu) * inv * gg.x + bb.x;
    float o1 = (v.y - mu) * inv * gg.y + bb.y;
    float o2 = (v.z - mu) * inv * gg.z + bb.z;
    float o3 = (v.w - mu) * inv * gg.w + bb.w;
    __half* yr = Y + row * (size_t)DMODEL + t * 4;
    *(__half2*)(yr)     = __halves2half2(__float2half(o0), __float2half(o1));
    *(__half2*)(yr + 2) = __halves2half2(__float2half(o2), __float2half(o3));
}

// ---------------- per-token differential attention (fp16 in, fp16 out) -------
// QKV fused input: row pitch 3072, q at +0, k at +1024, v at +2048.
__global__ __launch_bounds__(64) void attn_kernel(const __half* __restrict__ QKV,
                                                  __half* __restrict__ O) {
    __shared__ float s_q[2][32][33];
    __shared__ float s_k[2][32][32];
    __shared__ float s_v[2][16][64];
    const int warp = threadIdx.x >> 5;
    const int lane = threadIdx.x & 31;
    const size_t t = (size_t)blockIdx.x * 2 + warp;
    const __half* q = QKV + t * QKVN;
    const __half* k = q + DMODEL;
    const __half* v = k + DMODEL;
    float (*qs)[33] = s_q[warp];
    float (*ks)[32] = s_k[warp];
    float (*vs)[64] = s_v[warp];

    for (int idx = lane * 2; idx < DMODEL; idx += 64) {
        int h = idx >> 6, r = idx & 63;
        int dd = r >> 1;
        float2 qv = __half22float2(*(const __half2*)(q + idx));
        float2 kv = __half22float2(*(const __half2*)(k + idx));
        float2 vv = __half22float2(*(const __half2*)(v + idx));
        qs[h][dd]      = qv.x * QSCALE;
        qs[16 + h][dd] = qv.y * QSCALE;
        ks[h][dd]      = kv.x;
        ks[16 + h][dd] = kv.y;
        ((float*)vs)[idx]     = vv.x;
        ((float*)vs)[idx + 1] = vv.y;
    }
    __syncwarp();
    float qr[32];
    #pragma unroll
    for (int d = 0; d < 32; d++) qr[d] = qs[lane][d];
    float p[32];
    #pragma unroll
    for (int j = 0; j < 32; j++) {
        float s = 0.0f;
        #pragma unroll
        for (int d = 0; d < 32; d++) s += qr[d] * ks[j][d];
        p[j] = s;
    }
    float mx = p[0];
    #pragma unroll
    for (int j = 1; j < 32; j++) mx = fmaxf(mx, p[j]);
    float sum = 0.0f;
    #pragma unroll
    for (int j = 0; j < 32; j++) { p[j] = expf(p[j] - mx); sum += p[j]; }
    float rinv = 1.0f / sum;
    __syncwarp();
    #pragma unroll
    for (int j = 0; j < 32; j++) qs[lane][j] = p[j] * rinv;
    __syncwarp();

    const float lam = g_lambda;
    const int a = lane & 15;
    const int half = lane >> 4;
    float accv[32];
    #pragma unroll
    for (int e = 0; e < 32; e++) accv[e] = 0.0f;
    #pragma unroll
    for (int h = 0; h < 16; h++) {
        float w = qs[a][h] - lam * qs[16 + a][16 + h];
        const float* vrow = &vs[h][half * 32];
        #pragma unroll
        for (int e = 0; e < 32; e++) accv[e] += w * vrow[e];
    }
    float ss = 0.0f;
    #pragma unroll
    for (int e = 0; e < 32; e++) ss += accv[e] * accv[e];
    ss += __shfl_xor_sync(0xffffffffu, ss, 16);
    float scale = rsqrtf(ss * (1.0f / 64.0f) + 1e-5f) * ONE_MINUS_LAMBDA_F;

    __half* o = O + t * (size_t)DMODEL + a * 64 + half * 32;
    #pragma unroll
    for (int e = 0; e < 32; e += 2) {
        *(__half2*)(o + e) = __halves2half2(__float2half(accv[e] * scale),
                                            __float2half(accv[e + 1] * scale));
    }
}

// ---------------- HMMA GEMM: 4 warps, warp tile 64x64, 4-stage, 1 sync/iter --
// A:[M,Ko] fp16, W:[N,Ko] fp16. acc += A*W^T.
// 128x128 CTA tile, 4 warps (2m x 2n, each 64x64), BK=32.
// 4 stages x 20 KB = 80 KB -> 2 CTAs/SM. Single __syncthreads per k-iter:
// slot written at iter kt ((kt+2)%4) was last read at iter kt-2, ordered by
// the sync at iter kt-1.
// EPI: 1=bias 2=relu 4=+res(fp32) 8=fp16 out (else fp32 out)
#define PITCH  80u
#define TILE   10240u             // 128 * 80
#define OFF_A  0u
#define OFF_W  10240u
#define STG    20480u             // per stage
#define GSMEM  81920              // 4 stages

template <int EPI>
__global__ __launch_bounds__(128, 2)
void mma_gemm(const __half* __restrict__ A, const __half* __restrict__ W,
              const float* __restrict__ bias, const float* __restrict__ res,
              float* __restrict__ C, __half* __restrict__ Chl, int Nn, int Ko) {
    extern __shared__ __align__(1024) char smem[];
    const uint32_t sb = smem_u32(smem);
    const int tid = threadIdx.x;
    const int wid = tid >> 5, lane = tid & 31;
    const int m0 = blockIdx.y * 128, n0 = blockIdx.x * 128;
    const int wm = wid & 1, wn = wid >> 1;
    const int nk = Ko >> 5;            // BK = 32

    const __half* srcA = A + (size_t)m0 * Ko;
    const __half* srcW = W + (size_t)n0 * Ko;

    const int ldrow0 = tid >> 2;          // 0..31
    const int ldseg  = tid & 3;           // 0..3  (4 x 16B = 64B payload/row)
    const uint32_t ldoff0 = (uint32_t)(ldrow0 * PITCH + ldseg * 16);

    const int lr = lane & 7, grp = lane >> 3;
    uint32_t aOff[4], bOff[4];
    #pragma unroll
    for (int mi = 0; mi < 4; mi++)
        aOff[mi] = (uint32_t)((wm * 64 + mi * 16 + lr + (grp & 1) * 8) * PITCH +
                              ((grp >> 1) * 8) * 2);
    #pragma unroll
    for (int nj = 0; nj < 4; nj++)
        bOff[nj] = (uint32_t)((wn * 64 + nj * 16 + lr + (grp >> 1) * 8) * PITCH +
                              ((grp & 1) * 8) * 2);

    float acc[4][8][4];
    #pragma unroll
    for (int i = 0; i < 4; i++)
        #pragma unroll
        for (int j = 0; j < 8; j++)
            #pragma unroll
            for (int e = 0; e < 4; e++) acc[i][j][e] = 0.0f;

    auto load_stage = [&](int kt, int buf) {
        uint32_t base = sb + (uint32_t)buf * STG;
        const __half* ap = srcA + kt * 32;
        const __half* wp = srcW + kt * 32;
        #pragma unroll
        for (int i = 0; i < 4; i++) {
            int row = ldrow0 + i * 32;
            uint32_t off = ldoff0 + (uint32_t)(i * 32 * PITCH);
            size_t roff = (size_t)row * Ko + ldseg * 8;
            cpasync16(base + OFF_A + off, ap + roff);
            cpasync16(base + OFF_W + off, wp + roff);
        }
        CP_COMMIT();
    };

    load_stage(0, 0);
    load_stage(1, 1);
    for (int kt = 0; kt < nk; kt++) {
        int buf = kt & 3;
        if (kt + 2 < nk) { load_stage(kt + 2, (kt + 2) & 3); CP_WAIT2(); }
        else if (kt + 1 < nk) { CP_WAIT1(); }
        else { CP_WAIT0(); }
        __syncthreads();
        uint32_t base = sb + (uint32_t)buf * STG;
        #pragma unroll
        for (int ks = 0; ks < 2; ks++) {
            uint32_t af[4][4];
            #pragma unroll
            for (int mi = 0; mi < 4; mi++)
                LDMX4(af[mi], base + OFF_A + aOff[mi] + ks * 32);
            uint32_t bf[8][2];
            #pragma unroll
            for (int nj = 0; nj < 4; nj++) {
                uint32_t th[4];
                LDMX4(th, base + OFF_W + bOff[nj] + ks * 32);
                bf[2 * nj][0] = th[0];     bf[2 * nj][1] = th[1];
                bf[2 * nj + 1][0] = th[2]; bf[2 * nj + 1][1] = th[3];
            }
            #pragma unroll
            for (int mi = 0; mi < 4; mi++)
                #pragma unroll
                for (int ni = 0; ni < 8; ni++)
                    mma16816(acc[mi][ni][0], acc[mi][ni][1], acc[mi][ni][2], acc[mi][ni][3],
                             af[mi][0], af[mi][1], af[mi][2], af[mi][3],
                             bf[ni][0], bf[ni][1]);
        }
        // no trailing sync: 4-stage ring gives 2 iterations of WAR slack
    }

    // epilogue
    const int gm = m0 + wm * 64;
    const int gn = n0 + wn * 64;
    const int rr = lane >> 2;
    const int cc = (lane & 3) * 2;
    #pragma unroll
    for (int mi = 0; mi < 4; mi++) {
        #pragma unroll
        for (int ni = 0; ni < 8; ni++) {
            int col = gn + ni * 8 + cc;
            float2 bv = make_float2(0.f, 0.f);
            if (EPI & 1) bv = *(const float2*)(bias + col);
            #pragma unroll
            for (int hh = 0; hh < 2; hh++) {
                int row = gm + mi * 16 + rr + hh * 8;
                float v0 = acc[mi][ni][2 * hh];
                float v1 = acc[mi][ni][2 * hh + 1];
                if (EPI & 1) { v0 += bv.x; v1 += bv.y; }
                if (EPI & 2) { v0 = fmaxf(v0, 0.0f); v1 = fmaxf(v1, 0.0f); }
                if (EPI & 4) {
                    float2 r2 = *(const float2*)(res + (size_t)row * Nn + col);
                    v0 += r2.x; v1 += r2.y;
                }
                if (EPI & 8) {
                    *(__half2*)(Chl + (size_t)row * Nn + col) =
                        __halves2half2(__float2half(v0), __float2half(v1));
                } else {
                    *(float2*)(C + (size_t)row * Nn + col) = make_float2(v0, v1);
                }
            }
        }
    }
}

// ---------------- launch ----------------
extern "C" void kernel_launch(void* const* d_in, const int* in_sizes, int n_in,
                              void* d_out, int out_size) {
    const float* x    = (const float*)d_in[0];
    const float* Wq   = (const float*)d_in[1];
    const float* Wk   = (const float*)d_in[2];
    const float* Wv   = (const float*)d_in[3];
    const float* lq1  = (const float*)d_in[4];
    const float* lq2  = (const float*)d_in[5];
    const float* lk1  = (const float*)d_in[6];
    const float* lk2  = (const float*)d_in[7];
    const float* Wo   = (const float*)d_in[8];
    const float* bo   = (const float*)d_in[9];
    const float* ln1g = (const float*)d_in[10];
    const float* ln1b = (const float*)d_in[11];
    const float* ln2g = (const float*)d_in[12];
    const float* ln2b = (const float*)d_in[13];
    const float* W1   = (const float*)d_in[14];
    const float* b1   = (const float*)d_in[15];
    const float* W2   = (const float*)d_in[16];
    const float* b2   = (const float*)d_in[17];
    float* out = (float*)d_out;

    __half *phbf, *pqkv, *pattnbf, *ph2bf, *pffnbf, *pwqkv, *pwo, *pw1, *pw2;
    float *pconn;
    cudaGetSymbolAddress((void**)&phbf,    g_hbf);
    cudaGetSymbolAddress((void**)&pqkv,    g_qkv);
    cudaGetSymbolAddress((void**)&pattnbf, g_attnbf);
    cudaGetSymbolAddress((void**)&pconn,   g_conn);
    cudaGetSymbolAddress((void**)&ph2bf,   g_h2bf);
    cudaGetSymbolAddress((void**)&pffnbf,  g_ffnbf);
    cudaGetSymbolAddress((void**)&pwqkv,   g_wqkv);
    cudaGetSymbolAddress((void**)&pwo,     g_wo);
    cudaGetSymbolAddress((void**)&pw1,     g_w1);
    cudaGetSymbolAddress((void**)&pw2,     g_w2);

    cudaFuncSetAttribute(mma_gemm<8>,  cudaFuncAttributeMaxDynamicSharedMemorySize, GSMEM);
    cudaFuncSetAttribute(mma_gemm<5>,  cudaFuncAttributeMaxDynamicSharedMemorySize, GSMEM);
    cudaFuncSetAttribute(mma_gemm<11>, cudaFuncAttributeMaxDynamicSharedMemorySize, GSMEM);

    lambda_kernel<<<1, 32>>>(lq1, lq2, lk1, lk2);

    // fused weight convert (12M elements)
    convert_all<<<(12 * WSEG) / 256, 256>>>(Wq, Wk, Wv, Wo, W1, W2,
                                            pwqkv, pwo, pw1, pw2);

    // LN1: x -> hbf
    ln_kernel<<<Mrows, 256>>>(x, ln1g, ln1b, phbf);

    // fused QKV: [M,1024] x [3072,1024]^T -> [M,3072] fp16
    dim3 gqkv(QKVN / 128, Mrows / 128);   // (24,128)
    mma_gemm<8><<<gqkv, 128, GSMEM>>>(phbf, pwqkv, nullptr, nullptr, nullptr, pqkv, QKVN, DMODEL);

    attn_kernel<<<Mrows / 2, 64>>>(pqkv, pattnbf);

    // conn = x + attn @ Wo^T + bo
    dim3 gq(DMODEL / 128, Mrows / 128);   // (8,128)
    mma_gemm<5><<<gq, 128, GSMEM>>>(pattnbf, pwo, bo, x, pconn, nullptr, DMODEL, DMODEL);

    // LN2: conn -> h2bf
    ln_kernel<<<Mrows, 256>>>(pconn, ln2g, ln2b, ph2bf);

    // ffn = relu(h2 @ W1^T + b1) -> fp16
    dim3 g1(FFDIM / 128, Mrows / 128);    // (32,128)
    mma_gemm<11><<<g1, 128, GSMEM>>>(ph2bf, pw1, b1, nullptr, nullptr, pffnbf, FFDIM, DMODEL);

    // out = conn + ffn @ W2^T + b2
    mma_gemm<5><<<gq, 128, GSMEM>>>(pffnbf, pw2, b2, pconn, out, nullptr, DMODEL, FFDIM);
}

// round 14
// speedup vs baseline: 1.2544x; 1.0029x over previous
#include <cuda_runtime.h>
#include <cuda_fp16.h>
#include <cstdint>
#include <cstddef>

#define Mrows   16384
#define DMODEL  1024
#define FFDIM   4096
#define QKVN    3072
#define LAMBDA_INIT_F        0.35550906759096926f
#define ONE_MINUS_LAMBDA_F   0.64449093240903074f
#define QSCALE               0.17677669529663687f

// ---------------- scratch (device globals; no runtime allocs) ----------------
__device__ __align__(256) __half g_hbf   [(size_t)Mrows * DMODEL];
__device__ __align__(256) __half g_qkv   [(size_t)Mrows * QKVN];
__device__ __align__(256) __half g_attnbf[(size_t)Mrows * DMODEL];
__device__ __align__(256) float  g_conn  [(size_t)Mrows * DMODEL];
__device__ __align__(256) __half g_h2bf  [(size_t)Mrows * DMODEL];
__device__ __align__(256) __half g_ffnbf [(size_t)Mrows * FFDIM];
__device__ __align__(256) __half g_wqkv  [(size_t)QKVN   * DMODEL];
__device__ __align__(256) __half g_wo    [(size_t)DMODEL * DMODEL];
__device__ __align__(256) __half g_w1    [(size_t)FFDIM  * DMODEL];
__device__ __align__(256) __half g_w2    [(size_t)DMODEL * FFDIM];
__device__ float g_lambda;

// ---------------- PTX helpers (base sm_103 target; no 'a' features) ----------
__device__ __forceinline__ uint32_t smem_u32(const void* p) {
    uint32_t a;
    asm("{ .reg .u64 t; cvta.to.shared.u64 t, %1; cvt.u32.u64 %0, t; }" : "=r"(a) : "l"(p));
    return a;
}
__device__ __forceinline__ void cpasync16(uint32_t d, const void* g) {
    asm volatile("cp.async.cg.shared.global [%0], [%1], 16;" :: "r"(d), "l"(g));
}
#define CP_COMMIT()  asm volatile("cp.async.commit_group;" ::: "memory")
#define CP_WAIT1()   asm volatile("cp.async.wait_group 1;" ::: "memory")
#define CP_WAIT0()   asm volatile("cp.async.wait_group 0;" ::: "memory")

#define LDMX4(r, addr) \
    asm volatile("ldmatrix.sync.aligned.m8n8.x4.shared.b16 {%0,%1,%2,%3}, [%4];" \
                 : "=r"((r)[0]), "=r"((r)[1]), "=r"((r)[2]), "=r"((r)[3]) : "r"(addr))

__device__ __forceinline__ void mma16816(float& c0, float& c1, float& c2, float& c3,
                                         uint32_t a0, uint32_t a1, uint32_t a2, uint32_t a3,
                                         uint32_t b0, uint32_t b1) {
    asm volatile(
        "mma.sync.aligned.m16n8k16.row.col.f32.f16.f16.f32 "
        "{%0,%1,%2,%3}, {%4,%5,%6,%7}, {%8,%9}, {%0,%1,%2,%3};"
        : "+f"(c0), "+f"(c1), "+f"(c2), "+f"(c3)
        : "r"(a0), "r"(a1), "r"(a2), "r"(a3), "r"(b0), "r"(b1));
}

// ---------------- lambda ----------------
__global__ void lambda_kernel(const float* __restrict__ lq1, const float* __restrict__ lq2,
                              const float* __restrict__ lk1, const float* __restrict__ lk2) {
    int l = threadIdx.x;
    float s1 = lq1[l] * lk1[l];
    float s2 = lq2[l] * lk2[l];
    #pragma unroll
    for (int o = 16; o; o >>= 1) {
        s1 += __shfl_xor_sync(0xffffffffu, s1, o);
        s2 += __shfl_xor_sync(0xffffffffu, s2, o);
    }
    if (l == 0) g_lambda = expf(s1) - expf(s2) + LAMBDA_INIT_F;
}

// ---------------- fused weight convert: all six fp32 -> fp16 -----------------
#define WSEG 1048576u   // DMODEL*DMODEL
__global__ void convert_all(const float* __restrict__ Wq, const float* __restrict__ Wk,
                            const float* __restrict__ Wv, const float* __restrict__ Wo,
                            const float* __restrict__ W1, const float* __restrict__ W2,
                            __half* __restrict__ dqkv, __half* __restrict__ dwo,
                            __half* __restrict__ dw1, __half* __restrict__ dw2) {
    uint32_t idx = blockIdx.x * 256u + threadIdx.x;   // total 12*WSEG
    if (idx < WSEG)            dqkv[idx] = __float2half(Wq[idx]);
    else if (idx < 2 * WSEG)   dqkv[idx] = __float2half(Wk[idx - WSEG]);
    else if (idx < 3 * WSEG)   dqkv[idx] = __float2half(Wv[idx - 2 * WSEG]);
    else if (idx < 4 * WSEG)   dwo[idx - 3 * WSEG] = __float2half(Wo[idx - 3 * WSEG]);
    else if (idx < 8 * WSEG)   dw1[idx - 4 * WSEG] = __float2half(W1[idx - 4 * WSEG]);
    else                       dw2[idx - 8 * WSEG] = __float2half(W2[idx - 8 * WSEG]);
}

// ---------------- LayerNorm: fp32 in -> fp16 out ------------------------------
__global__ __launch_bounds__(256) void ln_kernel(const float* __restrict__ X,
                                                 const float* __restrict__ G,
                                                 const float* __restrict__ Bb,
                                                 __half* __restrict__ Y) {
    size_t row = blockIdx.x;
    int t = threadIdx.x;
    const float4 v = ((const float4*)(X + row * DMODEL))[t];
    float s  = v.x + v.y + v.z + v.w;
    float ss = v.x * v.x + v.y * v.y + v.z * v.z + v.w * v.w;
    #pragma unroll
    for (int o = 16; o; o >>= 1) {
        s  += __shfl_xor_sync(0xffffffffu, s,  o);
        ss += __shfl_xor_sync(0xffffffffu, ss, o);
    }
    __shared__ float sh_s[8], sh_ss[8];
    int w = t >> 5, l = t & 31;
    if (l == 0) { sh_s[w] = s; sh_ss[w] = ss; }
    __syncthreads();
    if (w == 0) {
        float a  = (l < 8) ? sh_s[l]  : 0.0f;
        float bq = (l < 8) ? sh_ss[l] : 0.0f;
        #pragma unroll
        for (int o = 4; o; o >>= 1) {
            a  += __shfl_xor_sync(0xffffffffu, a,  o);
            bq += __shfl_xor_sync(0xffffffffu, bq, o);
        }
        if (l == 0) { sh_s[0] = a; sh_ss[0] = bq; }
    }
    __syncthreads();
    float mu  = sh_s[0] * (1.0f / DMODEL);
    float var = sh_ss[0] * (1.0f / DMODEL) - mu * mu;
    float inv = rsqrtf(var + 1e-5f);
    const float4 gg = ((const float4*)G)[t];
    const float4 bb = ((const float4*)Bb)[t];
    float o0 = (v.x - mu) * inv * gg.x + bb.x;
    float o1 = (v.y - mu) * inv * gg.y + bb.y;
    float o2 = (v.z - mu) * inv * gg.z + bb.z;
    float o3 = (v.w - mu) * inv * gg.w + bb.w;
    __half* yr = Y + row * (size_t)DMODEL + t * 4;
    *(__half2*)(yr)     = __halves2half2(__float2half(o0), __float2half(o1));
    *(__half2*)(yr + 2) = __halves2half2(__float2half(o2), __float2half(o3));
}

// ---------------- per-token differential attention (fp16 in, fp16 out) -------
// QKV fused input: row pitch 3072, q at +0, k at +1024, v at +2048.
__global__ __launch_bounds__(64) void attn_kernel(const __half* __restrict__ QKV,
                                                  __half* __restrict__ O) {
    __shared__ float s_q[2][32][33];
    __shared__ float s_k[2][32][32];
    __shared__ float s_v[2][16][64];
    const int warp = threadIdx.x >> 5;
    const int lane = threadIdx.x & 31;
    const size_t t = (size_t)blockIdx.x * 2 + warp;
    const __half* q = QKV + t * QKVN;
    const __half* k = q + DMODEL;
    const __half* v = k + DMODEL;
    float (*qs)[33] = s_q[warp];
    float (*ks)[32] = s_k[warp];
    float (*vs)[64] = s_v[warp];

    for (int idx = lane * 2; idx < DMODEL; idx += 64) {
        int h = idx >> 6, r = idx & 63;
        int dd = r >> 1;
        float2 qv = __half22float2(*(const __half2*)(q + idx));
        float2 kv = __half22float2(*(const __half2*)(k + idx));
        float2 vv = __half22float2(*(const __half2*)(v + idx));
        qs[h][dd]      = qv.x * QSCALE;
        qs[16 + h][dd] = qv.y * QSCALE;
        ks[h][dd]      = kv.x;
        ks[16 + h][dd] = kv.y;
        ((float*)vs)[idx]     = vv.x;
        ((float*)vs)[idx + 1] = vv.y;
    }
    __syncwarp();
    float qr[32];
    #pragma unroll
    for (int d = 0; d < 32; d++) qr[d] = qs[lane][d];
    float p[32];
    #pragma unroll
    for (int j = 0; j < 32; j++) {
        float s = 0.0f;
        #pragma unroll
        for (int d = 0; d < 32; d++) s += qr[d] * ks[j][d];
        p[j] = s;
    }
    float mx = p[0];
    #pragma unroll
    for (int j = 1; j < 32; j++) mx = fmaxf(mx, p[j]);
    float sum = 0.0f;
    #pragma unroll
    for (int j = 0; j < 32; j++) { p[j] = expf(p[j] - mx); sum += p[j]; }
    float rinv = 1.0f / sum;
    __syncwarp();
    #pragma unroll
    for (int j = 0; j < 32; j++) qs[lane][j] = p[j] * rinv;
    __syncwarp();

    const float lam = g_lambda;
    const int a = lane & 15;
    const int half = lane >> 4;
    float accv[32];
    #pragma unroll
    for (int e = 0; e < 32; e++) accv[e] = 0.0f;
    #pragma unroll
    for (int h = 0; h < 16; h++) {
        float w = qs[a][h] - lam * qs[16 + a][16 + h];
        const float* vrow = &vs[h][half * 32];
        #pragma unroll
        for (int e = 0; e < 32; e++) accv[e] += w * vrow[e];
    }
    float ss = 0.0f;
    #pragma unroll
    for (int e = 0; e < 32; e++) ss += accv[e] * accv[e];
    ss += __shfl_xor_sync(0xffffffffu, ss, 16);
    float scale = rsqrtf(ss * (1.0f / 64.0f) + 1e-5f) * ONE_MINUS_LAMBDA_F;

    __half* o = O + t * (size_t)DMODEL + a * 64 + half * 32;
    #pragma unroll
    for (int e = 0; e < 32; e += 2) {
        *(__half2*)(o + e) = __halves2half2(__float2half(accv[e] * scale),
                                            __float2half(accv[e + 1] * scale));
    }
}

// ---------------- HMMA GEMM: 64x64 warp tile, 4-stage, fragment pipelining ---
// A:[M,Ko] fp16, W:[N,Ko] fp16. acc += A*W^T.
// 128x128 CTA tile, 4 warps (2m x 2n), BK=32, 4-stage smem ring (80 KB,
// 2 CTAs/SM), single __syncthreads per k-iter, and register double-buffered
// fragments so every LDSM batch is covered by the other half-step's HMMAs.
// EPI: 1=bias 2=relu 4=+res(fp32) 8=fp16 out (else fp32 out)
#define PITCH  80u
#define TILE   10240u             // 128 * 80
#define OFF_A  0u
#define OFF_W  10240u
#define STG    20480u             // per stage
#define GSMEM  81920              // 4 stages

template <int EPI>
__global__ __launch_bounds__(128, 2)
void mma_gemm(const __half* __restrict__ A, const __half* __restrict__ W,
              const float* __restrict__ bias, const float* __restrict__ res,
              float* __restrict__ C, __half* __restrict__ Chl, int Nn, int Ko) {
    extern __shared__ __align__(1024) char smem[];
    const uint32_t sb = smem_u32(smem);
    const int tid = threadIdx.x;
    const int wid = tid >> 5, lane = tid & 31;
    const int m0 = blockIdx.y * 128, n0 = blockIdx.x * 128;
    const int wm = wid & 1, wn = wid >> 1;
    const int nk = Ko >> 5;            // BK = 32

    const __half* srcA = A + (size_t)m0 * Ko;
    const __half* srcW = W + (size_t)n0 * Ko;

    const int ldrow0 = tid >> 2;          // 0..31
    const int ldseg  = tid & 3;           // 0..3  (4 x 16B = 64B payload/row)
    const uint32_t ldoff0 = (uint32_t)(ldrow0 * PITCH + ldseg * 16);

    const int lr = lane & 7, grp = lane >> 3;
    uint32_t aOff[4], bOff[4];
    #pragma unroll
    for (int mi = 0; mi < 4; mi++)
        aOff[mi] = (uint32_t)((wm * 64 + mi * 16 + lr + (grp & 1) * 8) * PITCH +
                              ((grp >> 1) * 8) * 2);
    #pragma unroll
    for (int nj = 0; nj < 4; nj++)
        bOff[nj] = (uint32_t)((wn * 64 + nj * 16 + lr + (grp >> 1) * 8) * PITCH +
                              ((grp & 1) * 8) * 2);

    float acc[4][8][4];
    #pragma unroll
    for (int i = 0; i < 4; i++)
        #pragma unroll
        for (int j = 0; j < 8; j++)
            #pragma unroll
            for (int e = 0; e < 4; e++) acc[i][j][e] = 0.0f;

    auto load_stage = [&](int kt, int buf) {
        uint32_t base = sb + (uint32_t)buf * STG;
        const __half* ap = srcA + kt * 32;
        const __half* wp = srcW + kt * 32;
        #pragma unroll
        for (int i = 0; i < 4; i++) {
            int row = ldrow0 + i * 32;
            uint32_t off = ldoff0 + (uint32_t)(i * 32 * PITCH);
            size_t roff = (size_t)row * Ko + ldseg * 8;
            cpasync16(base + OFF_A + off, ap + roff);
            cpasync16(base + OFF_W + off, wp + roff);
        }
        CP_COMMIT();
    };

    // fragment sets (double-buffered in registers)
    uint32_t afA[4][4], bfA[8][2];   // set A
    uint32_t afB[4][4], bfB[8][2];   // set B

    auto ldsm_set = [&](uint32_t base, int ks, uint32_t af[4][4], uint32_t bf[8][2]) {
        #pragma unroll
        for (int mi = 0; mi < 4; mi++)
            LDMX4(af[mi], base + OFF_A + aOff[mi] + ks * 32);
        #pragma unroll
        for (int nj = 0; nj < 4; nj++) {
            uint32_t th[4];
            LDMX4(th, base + OFF_W + bOff[nj] + ks * 32);
            bf[2 * nj][0] = th[0];     bf[2 * nj][1] = th[1];
            bf[2 * nj + 1][0] = th[2]; bf[2 * nj + 1][1] = th[3];
        }
    };
    auto mma_set = [&](uint32_t af[4][4], uint32_t bf[8][2]) {
        #pragma unroll
        for (int mi = 0; mi < 4; mi++)
            #pragma unroll
            for (int ni = 0; ni < 8; ni++)
                mma16816(acc[mi][ni][0], acc[mi][ni][1], acc[mi][ni][2], acc[mi][ni][3],
                         af[mi][0], af[mi][1], af[mi][2], af[mi][3],
                         bf[ni][0], bf[ni][1]);
    };

    // prologue: stages 0,1 in flight; stage 0 visible; fragA = (0, ks0)
    load_stage(0, 0);
    load_stage(1, 1);
    CP_WAIT1();
    __syncthreads();
    ldsm_set(sb, 0, afA, bfA);

    for (int kt = 0; kt < nk; kt++) {
        uint32_t baseCur = sb + (uint32_t)(kt & 3) * STG;
        // ks0: prefetch ks1 fragments, kick next-next stage, compute ks0
        ldsm_set(baseCur, 1, afB, bfB);
        if (kt + 2 < nk) load_stage(kt + 2, (kt + 2) & 3);
        mma_set(afA, bfA);
        // ks1: make stage kt+1 visible, prefetch its ks0 fragments, compute ks1
        if (kt + 1 < nk) {
            if (kt + 2 < nk) { CP_WAIT1(); } else { CP_WAIT0(); }
            __syncthreads();
            uint32_t baseNext = sb + (uint32_t)((kt + 1) & 3) * STG;
            ldsm_set(baseNext, 0, afA, bfA);
        }
        mma_set(afB, bfB);
    }

    // epilogue
    const int gm = m0 + wm * 64;
    const int gn = n0 + wn * 64;
    const int rr = lane >> 2;
    const int cc = (lane & 3) * 2;
    #pragma unroll
    for (int mi = 0; mi < 4; mi++) {
        #pragma unroll
        for (int ni = 0; ni < 8; ni++) {
            int col = gn + ni * 8 + cc;
            float2 bv = make_float2(0.f, 0.f);
            if (EPI & 1) bv = *(const float2*)(bias + col);
            #pragma unroll
            for (int hh = 0; hh < 2; hh++) {
                int row = gm + mi * 16 + rr + hh * 8;
                float v0 = acc[mi][ni][2 * hh];
                float v1 = acc[mi][ni][2 * hh + 1];
                if (EPI & 1) { v0 += bv.x; v1 += bv.y; }
                if (EPI & 2) { v0 = fmaxf(v0, 0.0f); v1 = fmaxf(v1, 0.0f); }
                if (EPI & 4) {
                    float2 r2 = *(const float2*)(res + (size_t)row * Nn + col);
                    v0 += r2.x; v1 += r2.y;
                }
                if (EPI & 8) {
                    *(__half2*)(Chl + (size_t)row * Nn + col) =
                        __halves2half2(__float2half(v0), __float2half(v1));
                } else {
                    *(float2*)(C + (size_t)row * Nn + col) = make_float2(v0, v1);
                }
            }
        }
    }
}

// ---------------- launch ----------------
extern "C" void kernel_launch(void* const* d_in, const int* in_sizes, int n_in,
                              void* d_out, int out_size) {
    const float* x    = (const float*)d_in[0];
    const float* Wq   = (const float*)d_in[1];
    const float* Wk   = (const float*)d_in[2];
    const float* Wv   = (const float*)d_in[3];
    const float* lq1  = (const float*)d_in[4];
    const float* lq2  = (const float*)d_in[5];
    const float* lk1  = (const float*)d_in[6];
    const float* lk2  = (const float*)d_in[7];
    const float* Wo   = (const float*)d_in[8];
    const float* bo   = (const float*)d_in[9];
    const float* ln1g = (const float*)d_in[10];
    const float* ln1b = (const float*)d_in[11];
    const float* ln2g = (const float*)d_in[12];
    const float* ln2b = (const float*)d_in[13];
    const float* W1   = (const float*)d_in[14];
    const float* b1   = (const float*)d_in[15];
    const float* W2   = (const float*)d_in[16];
    const float* b2   = (const float*)d_in[17];
    float* out = (float*)d_out;

    __half *phbf, *pqkv, *pattnbf, *ph2bf, *pffnbf, *pwqkv, *pwo, *pw1, *pw2;
    float *pconn;
    cudaGetSymbolAddress((void**)&phbf,    g_hbf);
    cudaGetSymbolAddress((void**)&pqkv,    g_qkv);
    cudaGetSymbolAddress((void**)&pattnbf, g_attnbf);
    cudaGetSymbolAddress((void**)&pconn,   g_conn);
    cudaGetSymbolAddress((void**)&ph2bf,   g_h2bf);
    cudaGetSymbolAddress((void**)&pffnbf,  g_ffnbf);
    cudaGetSymbolAddress((void**)&pwqkv,   g_wqkv);
    cudaGetSymbolAddress((void**)&pwo,     g_wo);
    cudaGetSymbolAddress((void**)&pw1,     g_w1);
    cudaGetSymbolAddress((void**)&pw2,     g_w2);

    cudaFuncSetAttribute(mma_gemm<8>,  cudaFuncAttributeMaxDynamicSharedMemorySize, GSMEM);
    cudaFuncSetAttribute(mma_gemm<5>,  cudaFuncAttributeMaxDynamicSharedMemorySize, GSMEM);
    cudaFuncSetAttribute(mma_gemm<11>, cudaFuncAttributeMaxDynamicSharedMemorySize, GSMEM);

    lambda_kernel<<<1, 32>>>(lq1, lq2, lk1, lk2);

    // fused weight convert (12M elements)
    convert_all<<<(12 * WSEG) / 256, 256>>>(Wq, Wk, Wv, Wo, W1, W2,
                                            pwqkv, pwo, pw1, pw2);

    // LN1: x -> hbf
    ln_kernel<<<Mrows, 256>>>(x, ln1g, ln1b, phbf);

    // fused QKV: [M,1024] x [3072,1024]^T -> [M,3072] fp16
    dim3 gqkv(QKVN / 128, Mrows / 128);   // (24,128)
    mma_gemm<8><<<gqkv, 128, GSMEM>>>(phbf, pwqkv, nullptr, nullptr, nullptr, pqkv, QKVN, DMODEL);

    attn_kernel<<<Mrows / 2, 64>>>(pqkv, pattnbf);

    // conn = x + attn @ Wo^T + bo
    dim3 gq(DMODEL / 128, Mrows / 128);   // (8,128)
    mma_gemm<5><<<gq, 128, GSMEM>>>(pattnbf, pwo, bo, x, pconn, nullptr, DMODEL, DMODEL);

    // LN2: conn -> h2bf
    ln_kernel<<<Mrows, 256>>>(pconn, ln2g, ln2b, ph2bf);

    // ffn = relu(h2 @ W1^T + b1) -> fp16
    dim3 g1(FFDIM / 128, Mrows / 128);    // (32,128)
    mma_gemm<11><<<g1, 128, GSMEM>>>(ph2bf, pw1, b1, nullptr, nullptr, pffnbf, FFDIM, DMODEL);

    // out = conn + ffn @ W2^T + b2
    mma_gemm<5><<<gq, 128, GSMEM>>>(pffnbf, pw2, b2, pconn, out, nullptr, DMODEL, FFDIM);
}

// round 15
// speedup vs baseline: 1.4078x; 1.1223x over previous
#include <cuda_runtime.h>
#include <cuda_fp16.h>
#include <cstdint>
#include <cstddef>

#define Mrows   16384
#define DMODEL  1024
#define FFDIM   4096
#define QKVN    3072
#define LAMBDA_INIT_F        0.35550906759096926f
#define ONE_MINUS_LAMBDA_F   0.64449093240903074f
#define QSCALE               0.17677669529663687f

// ---------------- scratch (device globals; no runtime allocs) ----------------
__device__ __align__(256) __half g_hbf   [(size_t)Mrows * DMODEL];
__device__ __align__(256) __half g_qkv   [(size_t)Mrows * QKVN];
__device__ __align__(256) __half g_attnbf[(size_t)Mrows * DMODEL];
__device__ __align__(256) float  g_conn  [(size_t)Mrows * DMODEL];
__device__ __align__(256) __half g_h2bf  [(size_t)Mrows * DMODEL];
__device__ __align__(256) __half g_ffnbf [(size_t)Mrows * FFDIM];
__device__ __align__(256) __half g_wqkv  [(size_t)QKVN   * DMODEL];
__device__ __align__(256) __half g_wo    [(size_t)DMODEL * DMODEL];
__device__ __align__(256) __half g_w1    [(size_t)FFDIM  * DMODEL];
__device__ __align__(256) __half g_w2    [(size_t)DMODEL * FFDIM];
__device__ float g_lambda;

// ---------------- PTX helpers (base sm_103 target; no 'a' features) ----------
__device__ __forceinline__ uint32_t smem_u32(const void* p) {
    uint32_t a;
    asm("{ .reg .u64 t; cvta.to.shared.u64 t, %1; cvt.u32.u64 %0, t; }" : "=r"(a) : "l"(p));
    return a;
}
__device__ __forceinline__ void cpasync16(uint32_t d, const void* g) {
    asm volatile("cp.async.cg.shared.global [%0], [%1], 16;" :: "r"(d), "l"(g));
}
#define CP_COMMIT()  asm volatile("cp.async.commit_group;" ::: "memory")
#define CP_WAIT1()   asm volatile("cp.async.wait_group 1;" ::: "memory")
#define CP_WAIT0()   asm volatile("cp.async.wait_group 0;" ::: "memory")

#define LDMX4(r, addr) \
    asm volatile("ldmatrix.sync.aligned.m8n8.x4.shared.b16 {%0,%1,%2,%3}, [%4];" \
                 : "=r"((r)[0]), "=r"((r)[1]), "=r"((r)[2]), "=r"((r)[3]) : "r"(addr))

__device__ __forceinline__ void mma16816(float& c0, float& c1, float& c2, float& c3,
                                         uint32_t a0, uint32_t a1, uint32_t a2, uint32_t a3,
                                         uint32_t b0, uint32_t b1) {
    asm volatile(
        "mma.sync.aligned.m16n8k16.row.col.f32.f16.f16.f32 "
        "{%0,%1,%2,%3}, {%4,%5,%6,%7}, {%8,%9}, {%0,%1,%2,%3};"
        : "+f"(c0), "+f"(c1), "+f"(c2), "+f"(c3)
        : "r"(a0), "r"(a1), "r"(a2), "r"(a3), "r"(b0), "r"(b1));
}

// ---------------- lambda ----------------
__global__ void lambda_kernel(const float* __restrict__ lq1, const float* __restrict__ lq2,
                              const float* __restrict__ lk1, const float* __restrict__ lk2) {
    int l = threadIdx.x;
    float s1 = lq1[l] * lk1[l];
    float s2 = lq2[l] * lk2[l];
    #pragma unroll
    for (int o = 16; o; o >>= 1) {
        s1 += __shfl_xor_sync(0xffffffffu, s1, o);
        s2 += __shfl_xor_sync(0xffffffffu, s2, o);
    }
    if (l == 0) g_lambda = expf(s1) - expf(s2) + LAMBDA_INIT_F;
}

// ---------------- fused weight convert: all six fp32 -> fp16 -----------------
#define WSEG 1048576u   // DMODEL*DMODEL
__global__ void convert_all(const float* __restrict__ Wq, const float* __restrict__ Wk,
                            const float* __restrict__ Wv, const float* __restrict__ Wo,
                            const float* __restrict__ W1, const float* __restrict__ W2,
                            __half* __restrict__ dqkv, __half* __restrict__ dwo,
                            __half* __restrict__ dw1, __half* __restrict__ dw2) {
    uint32_t idx = blockIdx.x * 256u + threadIdx.x;   // total 12*WSEG
    if (idx < WSEG)            dqkv[idx] = __float2half(Wq[idx]);
    else if (idx < 2 * WSEG)   dqkv[idx] = __float2half(Wk[idx - WSEG]);
    else if (idx < 3 * WSEG)   dqkv[idx] = __float2half(Wv[idx - 2 * WSEG]);
    else if (idx < 4 * WSEG)   dwo[idx - 3 * WSEG] = __float2half(Wo[idx - 3 * WSEG]);
    else if (idx < 8 * WSEG)   dw1[idx - 4 * WSEG] = __float2half(W1[idx - 4 * WSEG]);
    else                       dw2[idx - 8 * WSEG] = __float2half(W2[idx - 8 * WSEG]);
}

// ---------------- LayerNorm: fp32 in -> fp16 out ------------------------------
__global__ __launch_bounds__(256) void ln_kernel(const float* __restrict__ X,
                                                 const float* __restrict__ G,
                                                 const float* __restrict__ Bb,
                                                 __half* __restrict__ Y) {
    size_t row = blockIdx.x;
    int t = threadIdx.x;
    const float4 v = ((const float4*)(X + row * DMODEL))[t];
    float s  = v.x + v.y + v.z + v.w;
    float ss = v.x * v.x + v.y * v.y + v.z * v.z + v.w * v.w;
    #pragma unroll
    for (int o = 16; o; o >>= 1) {
        s  += __shfl_xor_sync(0xffffffffu, s,  o);
        ss += __shfl_xor_sync(0xffffffffu, ss, o);
    }
    __shared__ float sh_s[8], sh_ss[8];
    int w = t >> 5, l = t & 31;
    if (l == 0) { sh_s[w] = s; sh_ss[w] = ss; }
    __syncthreads();
    if (w == 0) {
        float a  = (l < 8) ? sh_s[l]  : 0.0f;
        float bq = (l < 8) ? sh_ss[l] : 0.0f;
        #pragma unroll
        for (int o = 4; o; o >>= 1) {
            a  += __shfl_xor_sync(0xffffffffu, a,  o);
            bq += __shfl_xor_sync(0xffffffffu, bq, o);
        }
        if (l == 0) { sh_s[0] = a; sh_ss[0] = bq; }
    }
    __syncthreads();
    float mu  = sh_s[0] * (1.0f / DMODEL);
    float var = sh_ss[0] * (1.0f / DMODEL) - mu * mu;
    float inv = rsqrtf(var + 1e-5f);
    const float4 gg = ((const float4*)G)[t];
    const float4 bb = ((const float4*)Bb)[t];
    float o0 = (v.x - mu) * inv * gg.x + bb.x;
    float o1 = (v.y - mu) * inv * gg.y + bb.y;
    float o2 = (v.z - mu) * inv * gg.z + bb.z;
    float o3 = (v.w - mu) * inv * gg.w + bb.w;
    __half* yr = Y + row * (size_t)DMODEL + t * 4;
    *(__half2*)(yr)     = __halves2half2(__float2half(o0), __float2half(o1));
    *(__half2*)(yr + 2) = __halves2half2(__float2half(o2), __float2half(o3));
}

// ---------------- per-token differential attention (fp16 in, fp16 out) -------
// QKV fused input: row pitch 3072, q at +0, k at +1024, v at +2048.
__global__ __launch_bounds__(64) void attn_kernel(const __half* __restrict__ QKV,
                                                  __half* __restrict__ O) {
    __shared__ float s_q[2][32][33];
    __shared__ float s_k[2][32][32];
    __shared__ float s_v[2][16][64];
    const int warp = threadIdx.x >> 5;
    const int lane = threadIdx.x & 31;
    const size_t t = (size_t)blockIdx.x * 2 + warp;
    const __half* q = QKV + t * QKVN;
    const __half* k = q + DMODEL;
    const __half* v = k + DMODEL;
    float (*qs)[33] = s_q[warp];
    float (*ks)[32] = s_k[warp];
    float (*vs)[64] = s_v[warp];

    for (int idx = lane * 2; idx < DMODEL; idx += 64) {
        int h = idx >> 6, r = idx & 63;
        int dd = r >> 1;
        float2 qv = __half22float2(*(const __half2*)(q + idx));
        float2 kv = __half22float2(*(const __half2*)(k + idx));
        float2 vv = __half22float2(*(const __half2*)(v + idx));
        qs[h][dd]      = qv.x * QSCALE;
        qs[16 + h][dd] = qv.y * QSCALE;
        ks[h][dd]      = kv.x;
        ks[16 + h][dd] = kv.y;
        ((float*)vs)[idx]     = vv.x;
        ((float*)vs)[idx + 1] = vv.y;
    }
    __syncwarp();
    float qr[32];
    #pragma unroll
    for (int d = 0; d < 32; d++) qr[d] = qs[lane][d];
    float p[32];
    #pragma unroll
    for (int j = 0; j < 32; j++) {
        float s = 0.0f;
        #pragma unroll
        for (int d = 0; d < 32; d++) s += qr[d] * ks[j][d];
        p[j] = s;
    }
    float mx = p[0];
    #pragma unroll
    for (int j = 1; j < 32; j++) mx = fmaxf(mx, p[j]);
    float sum = 0.0f;
    #pragma unroll
    for (int j = 0; j < 32; j++) { p[j] = expf(p[j] - mx); sum += p[j]; }
    float rinv = 1.0f / sum;
    __syncwarp();
    #pragma unroll
    for (int j = 0; j < 32; j++) qs[lane][j] = p[j] * rinv;
    __syncwarp();

    const float lam = g_lambda;
    const int a = lane & 15;
    const int half = lane >> 4;
    float accv[32];
    #pragma unroll
    for (int e = 0; e < 32; e++) accv[e] = 0.0f;
    #pragma unroll
    for (int h = 0; h < 16; h++) {
        float w = qs[a][h] - lam * qs[16 + a][16 + h];
        const float* vrow = &vs[h][half * 32];
        #pragma unroll
        for (int e = 0; e < 32; e++) accv[e] += w * vrow[e];
    }
    float ss = 0.0f;
    #pragma unroll
    for (int e = 0; e < 32; e++) ss += accv[e] * accv[e];
    ss += __shfl_xor_sync(0xffffffffu, ss, 16);
    float scale = rsqrtf(ss * (1.0f / 64.0f) + 1e-5f) * ONE_MINUS_LAMBDA_F;

    __half* o = O + t * (size_t)DMODEL + a * 64 + half * 32;
    #pragma unroll
    for (int e = 0; e < 32; e += 2) {
        *(__half2*)(o + e) = __halves2half2(__float2half(accv[e] * scale),
                                            __float2half(accv[e + 1] * scale));
    }
}

// ---------------- HMMA GEMM: 64x64 warp tile, XOR-swizzled smem, 3-stage -----
// A:[M,Ko] fp16, W:[N,Ko] fp16. acc += A*W^T.
// 128x128 CTA tile, 4 warps (2m x 2n), BK=32.
// Smem layout: 128B pitch, 16B chunk at physical slot (seg ^ (row&7)) —
// conflict-free for both cp.async stores and ldmatrix reads (4-phase floor).
// 3-stage ring (96 KB -> 2 CTAs/SM), one __syncthreads per k-iter; stage
// kt+2 is loaded AFTER the sync so its slot ((kt-1)%3) is WAR-safe.
// EPI: 1=bias 2=relu 4=+res(fp32) 8=fp16 out (else fp32 out)
#define PITCH  128u
#define TILE   16384u             // 128 * 128
#define OFF_A  0u
#define OFF_W  16384u
#define STG    32768u             // per stage
#define GSMEM  98304              // 3 stages

template <int EPI>
__global__ __launch_bounds__(128, 2)
void mma_gemm(const __half* __restrict__ A, const __half* __restrict__ W,
              const float* __restrict__ bias, const float* __restrict__ res,
              float* __restrict__ C, __half* __restrict__ Chl, int Nn, int Ko) {
    extern __shared__ __align__(1024) char smem[];
    const uint32_t sb = smem_u32(smem);
    const int tid = threadIdx.x;
    const int wid = tid >> 5, lane = tid & 31;
    const int m0 = blockIdx.y * 128, n0 = blockIdx.x * 128;
    const int wm = wid & 1, wn = wid >> 1;
    const int nk = Ko >> 5;            // BK = 32

    const __half* srcA = A + (size_t)m0 * Ko;
    const __half* srcW = W + (size_t)n0 * Ko;

    // cp.async mapping: 128 thr -> 32 rows x 4 segs (16B); 4 row-iters/tile
    const int ldrow0 = tid >> 2;          // 0..31
    const int ldseg  = tid & 3;           // 0..3

    // ldmatrix per-lane swizzled offsets (ks toggles via XOR 0x20)
    const int lr = lane & 7, grp = lane >> 3;
    uint32_t aOff[4], bOff[4];
    #pragma unroll
    for (int mi = 0; mi < 4; mi++) {
        int r = wm * 64 + mi * 16 + lr + (grp & 1) * 8;
        int c = grp >> 1;
        aOff[mi] = (uint32_t)(r * 128 + ((c ^ (r & 7)) * 16));
    }
    #pragma unroll
    for (int nj = 0; nj < 4; nj++) {
        int r = wn * 64 + nj * 16 + lr + (grp >> 1) * 8;
        int c = grp & 1;
        bOff[nj] = (uint32_t)(r * 128 + ((c ^ (r & 7)) * 16));
    }

    float acc[4][8][4];
    #pragma unroll
    for (int i = 0; i < 4; i++)
        #pragma unroll
        for (int j = 0; j < 8; j++)
            #pragma unroll
            for (int e = 0; e < 4; e++) acc[i][j][e] = 0.0f;

    auto load_stage = [&](int kt, int buf) {
        uint32_t base = sb + (uint32_t)buf * STG;
        const __half* ap = srcA + kt * 32;
        const __half* wp = srcW + kt * 32;
        #pragma unroll
        for (int i = 0; i < 4; i++) {
            int row = ldrow0 + i * 32;
            uint32_t off = (uint32_t)(row * 128 + ((ldseg ^ (row & 7)) * 16));
            size_t roff = (size_t)row * Ko + ldseg * 8;
            cpasync16(base + OFF_A + off, ap + roff);
            cpasync16(base + OFF_W + off, wp + roff);
        }
        CP_COMMIT();
    };

    load_stage(0, 0);
    load_stage(1, 1);
    for (int kt = 0; kt < nk; kt++) {
        int buf = kt % 3;
        if (kt + 1 < nk) { CP_WAIT1(); } else { CP_WAIT0(); }
        __syncthreads();
        if (kt + 2 < nk) load_stage(kt + 2, (kt + 2) % 3);
        uint32_t base = sb + (uint32_t)buf * STG;
        #pragma unroll
        for (int ks = 0; ks < 2; ks++) {
            const uint32_t kx = (uint32_t)ks << 5;     // XOR on chunk bit 1
            uint32_t af[4][4];
            #pragma unroll
            for (int mi = 0; mi < 4; mi++)
                LDMX4(af[mi], base + OFF_A + (aOff[mi] ^ kx));
            uint32_t bf[8][2];
            #pragma unroll
            for (int nj = 0; nj < 4; nj++) {
                uint32_t th[4];
                LDMX4(th, base + OFF_W + (bOff[nj] ^ kx));
                bf[2 * nj][0] = th[0];     bf[2 * nj][1] = th[1];
                bf[2 * nj + 1][0] = th[2]; bf[2 * nj + 1][1] = th[3];
            }
            #pragma unroll
            for (int mi = 0; mi < 4; mi++)
                #pragma unroll
                for (int ni = 0; ni < 8; ni++)
                    mma16816(acc[mi][ni][0], acc[mi][ni][1], acc[mi][ni][2], acc[mi][ni][3],
                             af[mi][0], af[mi][1], af[mi][2], af[mi][3],
                             bf[ni][0], bf[ni][1]);
        }
    }

    // epilogue
    const int gm = m0 + wm * 64;
    const int gn = n0 + wn * 64;
    const int rr = lane >> 2;
    const int cc = (lane & 3) * 2;
    #pragma unroll
    for (int mi = 0; mi < 4; mi++) {
        #pragma unroll
        for (int ni = 0; ni < 8; ni++) {
            int col = gn + ni * 8 + cc;
            float2 bv = make_float2(0.f, 0.f);
            if (EPI & 1) bv = *(const float2*)(bias + col);
            #pragma unroll
            for (int hh = 0; hh < 2; hh++) {
                int row = gm + mi * 16 + rr + hh * 8;
                float v0 = acc[mi][ni][2 * hh];
                float v1 = acc[mi][ni][2 * hh + 1];
                if (EPI & 1) { v0 += bv.x; v1 += bv.y; }
                if (EPI & 2) { v0 = fmaxf(v0, 0.0f); v1 = fmaxf(v1, 0.0f); }
                if (EPI & 4) {
                    float2 r2 = *(const float2*)(res + (size_t)row * Nn + col);
                    v0 += r2.x; v1 += r2.y;
                }
                if (EPI & 8) {
                    *(__half2*)(Chl + (size_t)row * Nn + col) =
                        __halves2half2(__float2half(v0), __float2half(v1));
                } else {
                    *(float2*)(C + (size_t)row * Nn + col) = make_float2(v0, v1);
                }
            }
        }
    }
}

// ---------------- launch ----------------
extern "C" void kernel_launch(void* const* d_in, const int* in_sizes, int n_in,
                              void* d_out, int out_size) {
    const float* x    = (const float*)d_in[0];
    const float* Wq   = (const float*)d_in[1];
    const float* Wk   = (const float*)d_in[2];
    const float* Wv   = (const float*)d_in[3];
    const float* lq1  = (const float*)d_in[4];
    const float* lq2  = (const float*)d_in[5];
    const float* lk1  = (const float*)d_in[6];
    const float* lk2  = (const float*)d_in[7];
    const float* Wo   = (const float*)d_in[8];
    const float* bo   = (const float*)d_in[9];
    const float* ln1g = (const float*)d_in[10];
    const float* ln1b = (const float*)d_in[11];
    const float* ln2g = (const float*)d_in[12];
    const float* ln2b = (const float*)d_in[13];
    const float* W1   = (const float*)d_in[14];
    const float* b1   = (const float*)d_in[15];
    const float* W2   = (const float*)d_in[16];
    const float* b2   = (const float*)d_in[17];
    float* out = (float*)d_out;

    __half *phbf, *pqkv, *pattnbf, *ph2bf, *pffnbf, *pwqkv, *pwo, *pw1, *pw2;
    float *pconn;
    cudaGetSymbolAddress((void**)&phbf,    g_hbf);
    cudaGetSymbolAddress((void**)&pqkv,    g_qkv);
    cudaGetSymbolAddress((void**)&pattnbf, g_attnbf);
    cudaGetSymbolAddress((void**)&pconn,   g_conn);
    cudaGetSymbolAddress((void**)&ph2bf,   g_h2bf);
    cudaGetSymbolAddress((void**)&pffnbf,  g_ffnbf);
    cudaGetSymbolAddress((void**)&pwqkv,   g_wqkv);
    cudaGetSymbolAddress((void**)&pwo,     g_wo);
    cudaGetSymbolAddress((void**)&pw1,     g_w1);
    cudaGetSymbolAddress((void**)&pw2,     g_w2);

    cudaFuncSetAttribute(mma_gemm<8>,  cudaFuncAttributeMaxDynamicSharedMemorySize, GSMEM);
    cudaFuncSetAttribute(mma_gemm<5>,  cudaFuncAttributeMaxDynamicSharedMemorySize, GSMEM);
    cudaFuncSetAttribute(mma_gemm<11>, cudaFuncAttributeMaxDynamicSharedMemorySize, GSMEM);

    lambda_kernel<<<1, 32>>>(lq1, lq2, lk1, lk2);

    // fused weight convert (12M elements)
    convert_all<<<(12 * WSEG) / 256, 256>>>(Wq, Wk, Wv, Wo, W1, W2,
                                            pwqkv, pwo, pw1, pw2);

    // LN1: x -> hbf
    ln_kernel<<<Mrows, 256>>>(x, ln1g, ln1b, phbf);

    // fused QKV: [M,1024] x [3072,1024]^T -> [M,3072] fp16
    dim3 gqkv(QKVN / 128, Mrows / 128);   // (24,128)
    mma_gemm<8><<<gqkv, 128, GSMEM>>>(phbf, pwqkv, nullptr, nullptr, nullptr, pqkv, QKVN, DMODEL);

    attn_kernel<<<Mrows / 2, 64>>>(pqkv, pattnbf);

    // conn = x + attn @ Wo^T + bo
    dim3 gq(DMODEL / 128, Mrows / 128);   // (8,128)
    mma_gemm<5><<<gq, 128, GSMEM>>>(pattnbf, pwo, bo, x, pconn, nullptr, DMODEL, DMODEL);

    // LN2: conn -> h2bf
    ln_kernel<<<Mrows, 256>>>(pconn, ln2g, ln2b, ph2bf);

    // ffn = relu(h2 @ W1^T + b1) -> fp16
    dim3 g1(FFDIM / 128, Mrows / 128);    // (32,128)
    mma_gemm<11><<<g1, 128, GSMEM>>>(ph2bf, pw1, b1, nullptr, nullptr, pffnbf, FFDIM, DMODEL);

    // out = conn + ffn @ W2^T + b2
    mma_gemm<5><<<gq, 128, GSMEM>>>(pffnbf, pw2, b2, pconn, out, nullptr, DMODEL, FFDIM);
}

// round 16
// speedup vs baseline: 1.4143x; 1.0046x over previous
#include <cuda_runtime.h>
#include <cuda_fp16.h>
#include <cstdint>
#include <cstddef>

#define Mrows   16384
#define DMODEL  1024
#define FFDIM   4096
#define QKVN    3072
#define LAMBDA_INIT_F        0.35550906759096926f
#define ONE_MINUS_LAMBDA_F   0.64449093240903074f
#define QSCALE               0.17677669529663687f

// ---------------- scratch (device globals; no runtime allocs) ----------------
__device__ __align__(256) __half g_hbf   [(size_t)Mrows * DMODEL];
__device__ __align__(256) __half g_qkv   [(size_t)Mrows * QKVN];
__device__ __align__(256) __half g_attnbf[(size_t)Mrows * DMODEL];
__device__ __align__(256) __half g_connh [(size_t)Mrows * DMODEL];   // fp16 now
__device__ __align__(256) __half g_h2bf  [(size_t)Mrows * DMODEL];
__device__ __align__(256) __half g_ffnbf [(size_t)Mrows * FFDIM];
__device__ __align__(256) __half g_wqkv  [(size_t)QKVN   * DMODEL];
__device__ __align__(256) __half g_wo    [(size_t)DMODEL * DMODEL];
__device__ __align__(256) __half g_w1    [(size_t)FFDIM  * DMODEL];
__device__ __align__(256) __half g_w2    [(size_t)DMODEL * FFDIM];
__device__ float g_lambda;

// ---------------- PTX helpers (base sm_103 target; no 'a' features) ----------
__device__ __forceinline__ uint32_t smem_u32(const void* p) {
    uint32_t a;
    asm("{ .reg .u64 t; cvta.to.shared.u64 t, %1; cvt.u32.u64 %0, t; }" : "=r"(a) : "l"(p));
    return a;
}
__device__ __forceinline__ void cpasync16(uint32_t d, const void* g) {
    asm volatile("cp.async.cg.shared.global [%0], [%1], 16;" :: "r"(d), "l"(g));
}
#define CP_COMMIT()  asm volatile("cp.async.commit_group;" ::: "memory")
#define CP_WAIT1()   asm volatile("cp.async.wait_group 1;" ::: "memory")
#define CP_WAIT0()   asm volatile("cp.async.wait_group 0;" ::: "memory")

#define LDMX4(r, addr) \
    asm volatile("ldmatrix.sync.aligned.m8n8.x4.shared.b16 {%0,%1,%2,%3}, [%4];" \
                 : "=r"((r)[0]), "=r"((r)[1]), "=r"((r)[2]), "=r"((r)[3]) : "r"(addr))

__device__ __forceinline__ void mma16816(float& c0, float& c1, float& c2, float& c3,
                                         uint32_t a0, uint32_t a1, uint32_t a2, uint32_t a3,
                                         uint32_t b0, uint32_t b1) {
    asm volatile(
        "mma.sync.aligned.m16n8k16.row.col.f32.f16.f16.f32 "
        "{%0,%1,%2,%3}, {%4,%5,%6,%7}, {%8,%9}, {%0,%1,%2,%3};"
        : "+f"(c0), "+f"(c1), "+f"(c2), "+f"(c3)
        : "r"(a0), "r"(a1), "r"(a2), "r"(a3), "r"(b0), "r"(b1));
}

// ---------------- lambda ----------------
__global__ void lambda_kernel(const float* __restrict__ lq1, const float* __restrict__ lq2,
                              const float* __restrict__ lk1, const float* __restrict__ lk2) {
    int l = threadIdx.x;
    float s1 = lq1[l] * lk1[l];
    float s2 = lq2[l] * lk2[l];
    #pragma unroll
    for (int o = 16; o; o >>= 1) {
        s1 += __shfl_xor_sync(0xffffffffu, s1, o);
        s2 += __shfl_xor_sync(0xffffffffu, s2, o);
    }
    if (l == 0) g_lambda = expf(s1) - expf(s2) + LAMBDA_INIT_F;
}

// ---------------- fused weight convert: all six fp32 -> fp16 -----------------
#define WSEG 1048576u   // DMODEL*DMODEL
__global__ void convert_all(const float* __restrict__ Wq, const float* __restrict__ Wk,
                            const float* __restrict__ Wv, const float* __restrict__ Wo,
                            const float* __restrict__ W1, const float* __restrict__ W2,
                            __half* __restrict__ dqkv, __half* __restrict__ dwo,
                            __half* __restrict__ dw1, __half* __restrict__ dw2) {
    uint32_t idx = blockIdx.x * 256u + threadIdx.x;   // total 12*WSEG
    if (idx < WSEG)            dqkv[idx] = __float2half(Wq[idx]);
    else if (idx < 2 * WSEG)   dqkv[idx] = __float2half(Wk[idx - WSEG]);
    else if (idx < 3 * WSEG)   dqkv[idx] = __float2half(Wv[idx - 2 * WSEG]);
    else if (idx < 4 * WSEG)   dwo[idx - 3 * WSEG] = __float2half(Wo[idx - 3 * WSEG]);
    else if (idx < 8 * WSEG)   dw1[idx - 4 * WSEG] = __float2half(W1[idx - 4 * WSEG]);
    else                       dw2[idx - 8 * WSEG] = __float2half(W2[idx - 8 * WSEG]);
}

// ---------------- LayerNorm (fp32 in) -> fp16 out -----------------------------
__global__ __launch_bounds__(256) void ln_kernel(const float* __restrict__ X,
                                                 const float* __restrict__ G,
                                                 const float* __restrict__ Bb,
                                                 __half* __restrict__ Y) {
    size_t row = blockIdx.x;
    int t = threadIdx.x;
    const float4 v = ((const float4*)(X + row * DMODEL))[t];
    float s  = v.x + v.y + v.z + v.w;
    float ss = v.x * v.x + v.y * v.y + v.z * v.z + v.w * v.w;
    #pragma unroll
    for (int o = 16; o; o >>= 1) {
        s  += __shfl_xor_sync(0xffffffffu, s,  o);
        ss += __shfl_xor_sync(0xffffffffu, ss, o);
    }
    __shared__ float sh_s[8], sh_ss[8];
    int w = t >> 5, l = t & 31;
    if (l == 0) { sh_s[w] = s; sh_ss[w] = ss; }
    __syncthreads();
    if (w == 0) {
        float a  = (l < 8) ? sh_s[l]  : 0.0f;
        float bq = (l < 8) ? sh_ss[l] : 0.0f;
        #pragma unroll
        for (int o = 4; o; o >>= 1) {
            a  += __shfl_xor_sync(0xffffffffu, a,  o);
            bq += __shfl_xor_sync(0xffffffffu, bq, o);
        }
        if (l == 0) { sh_s[0] = a; sh_ss[0] = bq; }
    }
    __syncthreads();
    float mu  = sh_s[0] * (1.0f / DMODEL);
    float var = sh_ss[0] * (1.0f / DMODEL) - mu * mu;
    float inv = rsqrtf(var + 1e-5f);
    const float4 gg = ((const float4*)G)[t];
    const float4 bb = ((const float4*)Bb)[t];
    float o0 = (v.x - mu) * inv * gg.x + bb.x;
    float o1 = (v.y - mu) * inv * gg.y + bb.y;
    float o2 = (v.z - mu) * inv * gg.z + bb.z;
    float o3 = (v.w - mu) * inv * gg.w + bb.w;
    __half* yr = Y + row * (size_t)DMODEL + t * 4;
    *(__half2*)(yr)     = __halves2half2(__float2half(o0), __float2half(o1));
    *(__half2*)(yr + 2) = __halves2half2(__float2half(o2), __float2half(o3));
}

// ---------------- LayerNorm (fp16 in) -> fp16 out -----------------------------
__global__ __launch_bounds__(256) void ln_kernel_h(const __half* __restrict__ X,
                                                   const float* __restrict__ G,
                                                   const float* __restrict__ Bb,
                                                   __half* __restrict__ Y) {
    size_t row = blockIdx.x;
    int t = threadIdx.x;
    const __half2 h01 = ((const __half2*)(X + row * DMODEL))[t * 2];
    const __half2 h23 = ((const __half2*)(X + row * DMODEL))[t * 2 + 1];
    float2 f01 = __half22float2(h01);
    float2 f23 = __half22float2(h23);
    float vx = f01.x, vy = f01.y, vz = f23.x, vw = f23.y;
    float s  = vx + vy + vz + vw;
    float ss = vx * vx + vy * vy + vz * vz + vw * vw;
    #pragma unroll
    for (int o = 16; o; o >>= 1) {
        s  += __shfl_xor_sync(0xffffffffu, s,  o);
        ss += __shfl_xor_sync(0xffffffffu, ss, o);
    }
    __shared__ float sh_s[8], sh_ss[8];
    int w = t >> 5, l = t & 31;
    if (l == 0) { sh_s[w] = s; sh_ss[w] = ss; }
    __syncthreads();
    if (w == 0) {
        float a  = (l < 8) ? sh_s[l]  : 0.0f;
        float bq = (l < 8) ? sh_ss[l] : 0.0f;
        #pragma unroll
        for (int o = 4; o; o >>= 1) {
            a  += __shfl_xor_sync(0xffffffffu, a,  o);
            bq += __shfl_xor_sync(0xffffffffu, bq, o);
        }
        if (l == 0) { sh_s[0] = a; sh_ss[0] = bq; }
    }
    __syncthreads();
    float mu  = sh_s[0] * (1.0f / DMODEL);
    float var = sh_ss[0] * (1.0f / DMODEL) - mu * mu;
    float inv = rsqrtf(var + 1e-5f);
    const float4 gg = ((const float4*)G)[t];
    const float4 bb = ((const float4*)Bb)[t];
    float o0 = (vx - mu) * inv * gg.x + bb.x;
    float o1 = (vy - mu) * inv * gg.y + bb.y;
    float o2 = (vz - mu) * inv * gg.z + bb.z;
    float o3 = (vw - mu) * inv * gg.w + bb.w;
    __half* yr = Y + row * (size_t)DMODEL + t * 4;
    *(__half2*)(yr)     = __halves2half2(__float2half(o0), __float2half(o1));
    *(__half2*)(yr + 2) = __halves2half2(__float2half(o2), __float2half(o3));
}

// ---------------- per-token differential attention (fp16 in, fp16 out) -------
__global__ __launch_bounds__(64) void attn_kernel(const __half* __restrict__ QKV,
                                                  __half* __restrict__ O) {
    __shared__ float s_q[2][32][33];
    __shared__ float s_k[2][32][32];
    __shared__ float s_v[2][16][64];
    const int warp = threadIdx.x >> 5;
    const int lane = threadIdx.x & 31;
    const size_t t = (size_t)blockIdx.x * 2 + warp;
    const __half* q = QKV + t * QKVN;
    const __half* k = q + DMODEL;
    const __half* v = k + DMODEL;
    float (*qs)[33] = s_q[warp];
    float (*ks)[32] = s_k[warp];
    float (*vs)[64] = s_v[warp];

    for (int idx = lane * 2; idx < DMODEL; idx += 64) {
        int h = idx >> 6, r = idx & 63;
        int dd = r >> 1;
        float2 qv = __half22float2(*(const __half2*)(q + idx));
        float2 kv = __half22float2(*(const __half2*)(k + idx));
        float2 vv = __half22float2(*(const __half2*)(v + idx));
        qs[h][dd]      = qv.x * QSCALE;
        qs[16 + h][dd] = qv.y * QSCALE;
        ks[h][dd]      = kv.x;
        ks[16 + h][dd] = kv.y;
        ((float*)vs)[idx]     = vv.x;
        ((float*)vs)[idx + 1] = vv.y;
    }
    __syncwarp();
    float qr[32];
    #pragma unroll
    for (int d = 0; d < 32; d++) qr[d] = qs[lane][d];
    float p[32];
    #pragma unroll
    for (int j = 0; j < 32; j++) {
        float s = 0.0f;
        #pragma unroll
        for (int d = 0; d < 32; d++) s += qr[d] * ks[j][d];
        p[j] = s;
    }
    float mx = p[0];
    #pragma unroll
    for (int j = 1; j < 32; j++) mx = fmaxf(mx, p[j]);
    float sum = 0.0f;
    #pragma unroll
    for (int j = 0; j < 32; j++) { p[j] = expf(p[j] - mx); sum += p[j]; }
    float rinv = 1.0f / sum;
    __syncwarp();
    #pragma unroll
    for (int j = 0; j < 32; j++) qs[lane][j] = p[j] * rinv;
    __syncwarp();

    const float lam = g_lambda;
    const int a = lane & 15;
    const int half = lane >> 4;
    float accv[32];
    #pragma unroll
    for (int e = 0; e < 32; e++) accv[e] = 0.0f;
    #pragma unroll
    for (int h = 0; h < 16; h++) {
        float w = qs[a][h] - lam * qs[16 + a][16 + h];
        const float* vrow = &vs[h][half * 32];
        #pragma unroll
        for (int e = 0; e < 32; e++) accv[e] += w * vrow[e];
    }
    float ss = 0.0f;
    #pragma unroll
    for (int e = 0; e < 32; e++) ss += accv[e] * accv[e];
    ss += __shfl_xor_sync(0xffffffffu, ss, 16);
    float scale = rsqrtf(ss * (1.0f / 64.0f) + 1e-5f) * ONE_MINUS_LAMBDA_F;

    __half* o = O + t * (size_t)DMODEL + a * 64 + half * 32;
    #pragma unroll
    for (int e = 0; e < 32; e += 2) {
        *(__half2*)(o + e) = __halves2half2(__float2half(accv[e] * scale),
                                            __float2half(accv[e + 1] * scale));
    }
}

// ---------------- HMMA GEMM: 64x64 warp tile, XOR-swizzled smem, 3-stage -----
// A:[M,Ko] fp16, W:[N,Ko] fp16. acc += A*W^T.
// EPI: 1=bias 2=relu 4=+res(fp32) 8=fp16 out (else fp32 out) 16=+res(fp16)
#define PITCH  128u
#define TILE   16384u             // 128 * 128
#define OFF_A  0u
#define OFF_W  16384u
#define STG    32768u             // per stage
#define GSMEM  98304              // 3 stages

template <int EPI>
__global__ __launch_bounds__(128, 2)
void mma_gemm(const __half* __restrict__ A, const __half* __restrict__ W,
              const float* __restrict__ bias, const float* __restrict__ res,
              const __half* __restrict__ resh,
              float* __restrict__ C, __half* __restrict__ Chl, int Nn, int Ko) {
    extern __shared__ __align__(1024) char smem[];
    const uint32_t sb = smem_u32(smem);
    const int tid = threadIdx.x;
    const int wid = tid >> 5, lane = tid & 31;
    const int m0 = blockIdx.y * 128, n0 = blockIdx.x * 128;
    const int wm = wid & 1, wn = wid >> 1;
    const int nk = Ko >> 5;            // BK = 32

    const __half* srcA = A + (size_t)m0 * Ko;
    const __half* srcW = W + (size_t)n0 * Ko;

    const int ldrow0 = tid >> 2;          // 0..31
    const int ldseg  = tid & 3;           // 0..3

    const int lr = lane & 7, grp = lane >> 3;
    uint32_t aOff[4], bOff[4];
    #pragma unroll
    for (int mi = 0; mi < 4; mi++) {
        int r = wm * 64 + mi * 16 + lr + (grp & 1) * 8;
        int c = grp >> 1;
        aOff[mi] = (uint32_t)(r * 128 + ((c ^ (r & 7)) * 16));
    }
    #pragma unroll
    for (int nj = 0; nj < 4; nj++) {
        int r = wn * 64 + nj * 16 + lr + (grp >> 1) * 8;
        int c = grp & 1;
        bOff[nj] = (uint32_t)(r * 128 + ((c ^ (r & 7)) * 16));
    }

    float acc[4][8][4];
    #pragma unroll
    for (int i = 0; i < 4; i++)
        #pragma unroll
        for (int j = 0; j < 8; j++)
            #pragma unroll
            for (int e = 0; e < 4; e++) acc[i][j][e] = 0.0f;

    auto load_stage = [&](int kt, int buf) {
        uint32_t base = sb + (uint32_t)buf * STG;
        const __half* ap = srcA + kt * 32;
        const __half* wp = srcW + kt * 32;
        #pragma unroll
        for (int i = 0; i < 4; i++) {
            int row = ldrow0 + i * 32;
            uint32_t off = (uint32_t)(row * 128 + ((ldseg ^ (row & 7)) * 16));
            size_t roff = (size_t)row * Ko + ldseg * 8;
            cpasync16(base + OFF_A + off, ap + roff);
            cpasync16(base + OFF_W + off, wp + roff);
        }
        CP_COMMIT();
    };

    load_stage(0, 0);
    load_stage(1, 1);
    for (int kt = 0; kt < nk; kt++) {
        int buf = kt % 3;
        if (kt + 1 < nk) { CP_WAIT1(); } else { CP_WAIT0(); }
        __syncthreads();
        if (kt + 2 < nk) load_stage(kt + 2, (kt + 2) % 3);
        uint32_t base = sb + (uint32_t)buf * STG;
        #pragma unroll
        for (int ks = 0; ks < 2; ks++) {
            const uint32_t kx = (uint32_t)ks << 5;
            uint32_t af[4][4];
            #pragma unroll
            for (int mi = 0; mi < 4; mi++)
                LDMX4(af[mi], base + OFF_A + (aOff[mi] ^ kx));
            uint32_t bf[8][2];
            #pragma unroll
            for (int nj = 0; nj < 4; nj++) {
                uint32_t th[4];
                LDMX4(th, base + OFF_W + (bOff[nj] ^ kx));
                bf[2 * nj][0] = th[0];     bf[2 * nj][1] = th[1];
                bf[2 * nj + 1][0] = th[2]; bf[2 * nj + 1][1] = th[3];
            }
            #pragma unroll
            for (int mi = 0; mi < 4; mi++)
                #pragma unroll
                for (int ni = 0; ni < 8; ni++)
                    mma16816(acc[mi][ni][0], acc[mi][ni][1], acc[mi][ni][2], acc[mi][ni][3],
                             af[mi][0], af[mi][1], af[mi][2], af[mi][3],
                             bf[ni][0], bf[ni][1]);
        }
    }

    // epilogue
    const int gm = m0 + wm * 64;
    const int gn = n0 + wn * 64;
    const int rr = lane >> 2;
    const int cc = (lane & 3) * 2;
    #pragma unroll
    for (int mi = 0; mi < 4; mi++) {
        #pragma unroll
        for (int ni = 0; ni < 8; ni++) {
            int col = gn + ni * 8 + cc;
            float2 bv = make_float2(0.f, 0.f);
            if (EPI & 1) bv = *(const float2*)(bias + col);
            #pragma unroll
            for (int hh = 0; hh < 2; hh++) {
                int row = gm + mi * 16 + rr + hh * 8;
                float v0 = acc[mi][ni][2 * hh];
                float v1 = acc[mi][ni][2 * hh + 1];
                if (EPI & 1) { v0 += bv.x; v1 += bv.y; }
                if (EPI & 2) { v0 = fmaxf(v0, 0.0f); v1 = fmaxf(v1, 0.0f); }
                if (EPI & 4) {
                    float2 r2 = *(const float2*)(res + (size_t)row * Nn + col);
                    v0 += r2.x; v1 += r2.y;
                }
                if (EPI & 16) {
                    float2 r2 = __half22float2(*(const __half2*)(resh + (size_t)row * Nn + col));
                    v0 += r2.x; v1 += r2.y;
                }
                if (EPI & 8) {
                    *(__half2*)(Chl + (size_t)row * Nn + col) =
                        __halves2half2(__float2half(v0), __float2half(v1));
                } else {
                    *(float2*)(C + (size_t)row * Nn + col) = make_float2(v0, v1);
                }
            }
        }
    }
}

// ---------------- launch ----------------
extern "C" void kernel_launch(void* const* d_in, const int* in_sizes, int n_in,
                              void* d_out, int out_size) {
    const float* x    = (const float*)d_in[0];
    const float* Wq   = (const float*)d_in[1];
    const float* Wk   = (const float*)d_in[2];
    const float* Wv   = (const float*)d_in[3];
    const float* lq1  = (const float*)d_in[4];
    const float* lq2  = (const float*)d_in[5];
    const float* lk1  = (const float*)d_in[6];
    const float* lk2  = (const float*)d_in[7];
    const float* Wo   = (const float*)d_in[8];
    const float* bo   = (const float*)d_in[9];
    const float* ln1g = (const float*)d_in[10];
    const float* ln1b = (const float*)d_in[11];
    const float* ln2g = (const float*)d_in[12];
    const float* ln2b = (const float*)d_in[13];
    const float* W1   = (const float*)d_in[14];
    const float* b1   = (const float*)d_in[15];
    const float* W2   = (const float*)d_in[16];
    const float* b2   = (const float*)d_in[17];
    float* out = (float*)d_out;

    __half *phbf, *pqkv, *pattnbf, *pconnh, *ph2bf, *pffnbf, *pwqkv, *pwo, *pw1, *pw2;
    cudaGetSymbolAddress((void**)&phbf,    g_hbf);
    cudaGetSymbolAddress((void**)&pqkv,    g_qkv);
    cudaGetSymbolAddress((void**)&pattnbf, g_attnbf);
    cudaGetSymbolAddress((void**)&pconnh,  g_connh);
    cudaGetSymbolAddress((void**)&ph2bf,   g_h2bf);
    cudaGetSymbolAddress((void**)&pffnbf,  g_ffnbf);
    cudaGetSymbolAddress((void**)&pwqkv,   g_wqkv);
    cudaGetSymbolAddress((void**)&pwo,     g_wo);
    cudaGetSymbolAddress((void**)&pw1,     g_w1);
    cudaGetSymbolAddress((void**)&pw2,     g_w2);

    cudaFuncSetAttribute(mma_gemm<8>,  cudaFuncAttributeMaxDynamicSharedMemorySize, GSMEM);
    cudaFuncSetAttribute(mma_gemm<13>, cudaFuncAttributeMaxDynamicSharedMemorySize, GSMEM);
    cudaFuncSetAttribute(mma_gemm<11>, cudaFuncAttributeMaxDynamicSharedMemorySize, GSMEM);
    cudaFuncSetAttribute(mma_gemm<17>, cudaFuncAttributeMaxDynamicSharedMemorySize, GSMEM);

    lambda_kernel<<<1, 32>>>(lq1, lq2, lk1, lk2);

    // fused weight convert (12M elements)
    convert_all<<<(12 * WSEG) / 256, 256>>>(Wq, Wk, Wv, Wo, W1, W2,
                                            pwqkv, pwo, pw1, pw2);

    // LN1: x (fp32) -> hbf (fp16)
    ln_kernel<<<Mrows, 256>>>(x, ln1g, ln1b, phbf);

    // fused QKV: [M,1024] x [3072,1024]^T -> [M,3072] fp16
    dim3 gqkv(QKVN / 128, Mrows / 128);   // (24,128)
    mma_gemm<8><<<gqkv, 128, GSMEM>>>(phbf, pwqkv, nullptr, nullptr, nullptr,
                                      nullptr, pqkv, QKVN, DMODEL);

    attn_kernel<<<Mrows / 2, 64>>>(pqkv, pattnbf);

    // conn = x + attn @ Wo^T + bo  -> fp16 (bias + fp32 res + fp16 out)
    dim3 gq(DMODEL / 128, Mrows / 128);   // (8,128)
    mma_gemm<13><<<gq, 128, GSMEM>>>(pattnbf, pwo, bo, x, nullptr,
                                     nullptr, pconnh, DMODEL, DMODEL);

    // LN2: conn (fp16) -> h2bf (fp16)
    ln_kernel_h<<<Mrows, 256>>>(pconnh, ln2g, ln2b, ph2bf);

    // ffn = relu(h2 @ W1^T + b1) -> fp16
    dim3 g1(FFDIM / 128, Mrows / 128);    // (32,128)
    mma_gemm<11><<<g1, 128, GSMEM>>>(ph2bf, pw1, b1, nullptr, nullptr,
                                     nullptr, pffnbf, FFDIM, DMODEL);

    // out = conn (fp16 res) + ffn @ W2^T + b2 -> fp32
    mma_gemm<17><<<gq, 128, GSMEM>>>(pffnbf, pw2, b2, nullptr, pconnh,
                                     out, nullptr, DMODEL, FFDIM);
}

// round 17
// speedup vs baseline: 1.4420x; 1.0195x over previous
#include <cuda_runtime.h>
#include <cuda_fp16.h>
#include <cstdint>
#include <cstddef>

#define Mrows   16384
#define DMODEL  1024
#define FFDIM   4096
#define QKVN    3072
#define LAMBDA_INIT_F        0.35550906759096926f
#define ONE_MINUS_LAMBDA_F   0.64449093240903074f
#define QSCALE               0.17677669529663687f

// ---------------- scratch (device globals; no runtime allocs) ----------------
__device__ __align__(256) __half g_hbf   [(size_t)Mrows * DMODEL];
__device__ __align__(256) __half g_qkv   [(size_t)Mrows * QKVN];
__device__ __align__(256) __half g_attnbf[(size_t)Mrows * DMODEL];
__device__ __align__(256) __half g_connh [(size_t)Mrows * DMODEL];
__device__ __align__(256) __half g_h2bf  [(size_t)Mrows * DMODEL];
__device__ __align__(256) __half g_ffnbf [(size_t)Mrows * FFDIM];
__device__ __align__(256) __half g_wqkv  [(size_t)QKVN   * DMODEL];
__device__ __align__(256) __half g_wo    [(size_t)DMODEL * DMODEL];
__device__ __align__(256) __half g_w1    [(size_t)FFDIM  * DMODEL];
__device__ __align__(256) __half g_w2    [(size_t)DMODEL * FFDIM];
__device__ float g_lambda;

// ---------------- PTX helpers (base sm_103 target; no 'a' features) ----------
__device__ __forceinline__ uint32_t smem_u32(const void* p) {
    uint32_t a;
    asm("{ .reg .u64 t; cvta.to.shared.u64 t, %1; cvt.u32.u64 %0, t; }" : "=r"(a) : "l"(p));
    return a;
}
__device__ __forceinline__ void cpasync16(uint32_t d, const void* g) {
    asm volatile("cp.async.cg.shared.global [%0], [%1], 16;" :: "r"(d), "l"(g));
}
#define CP_COMMIT()  asm volatile("cp.async.commit_group;" ::: "memory")
#define CP_WAIT1()   asm volatile("cp.async.wait_group 1;" ::: "memory")
#define CP_WAIT0()   asm volatile("cp.async.wait_group 0;" ::: "memory")

#define LDMX4(r, addr) \
    asm volatile("ldmatrix.sync.aligned.m8n8.x4.shared.b16 {%0,%1,%2,%3}, [%4];" \
                 : "=r"((r)[0]), "=r"((r)[1]), "=r"((r)[2]), "=r"((r)[3]) : "r"(addr))

__device__ __forceinline__ void mma16816(float& c0, float& c1, float& c2, float& c3,
                                         uint32_t a0, uint32_t a1, uint32_t a2, uint32_t a3,
                                         uint32_t b0, uint32_t b1) {
    asm volatile(
        "mma.sync.aligned.m16n8k16.row.col.f32.f16.f16.f32 "
        "{%0,%1,%2,%3}, {%4,%5,%6,%7}, {%8,%9}, {%0,%1,%2,%3};"
        : "+f"(c0), "+f"(c1), "+f"(c2), "+f"(c3)
        : "r"(a0), "r"(a1), "r"(a2), "r"(a3), "r"(b0), "r"(b1));
}

// ---------------- lambda ----------------
__global__ void lambda_kernel(const float* __restrict__ lq1, const float* __restrict__ lq2,
                              const float* __restrict__ lk1, const float* __restrict__ lk2) {
    int l = threadIdx.x;
    float s1 = lq1[l] * lk1[l];
    float s2 = lq2[l] * lk2[l];
    #pragma unroll
    for (int o = 16; o; o >>= 1) {
        s1 += __shfl_xor_sync(0xffffffffu, s1, o);
        s2 += __shfl_xor_sync(0xffffffffu, s2, o);
    }
    if (l == 0) g_lambda = expf(s1) - expf(s2) + LAMBDA_INIT_F;
}

// ---------------- fused weight convert: all six fp32 -> fp16 -----------------
#define WSEG 1048576u   // DMODEL*DMODEL
__global__ void convert_all(const float* __restrict__ Wq, const float* __restrict__ Wk,
                            const float* __restrict__ Wv, const float* __restrict__ Wo,
                            const float* __restrict__ W1, const float* __restrict__ W2,
                            __half* __restrict__ dqkv, __half* __restrict__ dwo,
                            __half* __restrict__ dw1, __half* __restrict__ dw2) {
    uint32_t idx = blockIdx.x * 256u + threadIdx.x;   // total 12*WSEG
    if (idx < WSEG)            dqkv[idx] = __float2half(Wq[idx]);
    else if (idx < 2 * WSEG)   dqkv[idx] = __float2half(Wk[idx - WSEG]);
    else if (idx < 3 * WSEG)   dqkv[idx] = __float2half(Wv[idx - 2 * WSEG]);
    else if (idx < 4 * WSEG)   dwo[idx - 3 * WSEG] = __float2half(Wo[idx - 3 * WSEG]);
    else if (idx < 8 * WSEG)   dw1[idx - 4 * WSEG] = __float2half(W1[idx - 4 * WSEG]);
    else                       dw2[idx - 8 * WSEG] = __float2half(W2[idx - 8 * WSEG]);
}

// ---------------- LayerNorm (fp32 in) -> fp16 out -----------------------------
__global__ __launch_bounds__(256) void ln_kernel(const float* __restrict__ X,
                                                 const float* __restrict__ G,
                                                 const float* __restrict__ Bb,
                                                 __half* __restrict__ Y) {
    size_t row = blockIdx.x;
    int t = threadIdx.x;
    const float4 v = ((const float4*)(X + row * DMODEL))[t];
    float s  = v.x + v.y + v.z + v.w;
    float ss = v.x * v.x + v.y * v.y + v.z * v.z + v.w * v.w;
    #pragma unroll
    for (int o = 16; o; o >>= 1) {
        s  += __shfl_xor_sync(0xffffffffu, s,  o);
        ss += __shfl_xor_sync(0xffffffffu, ss, o);
    }
    __shared__ float sh_s[8], sh_ss[8];
    int w = t >> 5, l = t & 31;
    if (l == 0) { sh_s[w] = s; sh_ss[w] = ss; }
    __syncthreads();
    if (w == 0) {
        float a  = (l < 8) ? sh_s[l]  : 0.0f;
        float bq = (l < 8) ? sh_ss[l] : 0.0f;
        #pragma unroll
        for (int o = 4; o; o >>= 1) {
            a  += __shfl_xor_sync(0xffffffffu, a,  o);
            bq += __shfl_xor_sync(0xffffffffu, bq, o);
        }
        if (l == 0) { sh_s[0] = a; sh_ss[0] = bq; }
    }
    __syncthreads();
    float mu  = sh_s[0] * (1.0f / DMODEL);
    float var = sh_ss[0] * (1.0f / DMODEL) - mu * mu;
    float inv = rsqrtf(var + 1e-5f);
    const float4 gg = ((const float4*)G)[t];
    const float4 bb = ((const float4*)Bb)[t];
    float o0 = (v.x - mu) * inv * gg.x + bb.x;
    float o1 = (v.y - mu) * inv * gg.y + bb.y;
    float o2 = (v.z - mu) * inv * gg.z + bb.z;
    float o3 = (v.w - mu) * inv * gg.w + bb.w;
    __half* yr = Y + row * (size_t)DMODEL + t * 4;
    *(__half2*)(yr)     = __halves2half2(__float2half(o0), __float2half(o1));
    *(__half2*)(yr + 2) = __halves2half2(__float2half(o2), __float2half(o3));
}

// ---------------- LayerNorm (fp16 in) -> fp16 out -----------------------------
__global__ __launch_bounds__(256) void ln_kernel_h(const __half* __restrict__ X,
                                                   const float* __restrict__ G,
                                                   const float* __restrict__ Bb,
                                                   __half* __restrict__ Y) {
    size_t row = blockIdx.x;
    int t = threadIdx.x;
    const __half2 h01 = ((const __half2*)(X + row * DMODEL))[t * 2];
    const __half2 h23 = ((const __half2*)(X + row * DMODEL))[t * 2 + 1];
    float2 f01 = __half22float2(h01);
    float2 f23 = __half22float2(h23);
    float vx = f01.x, vy = f01.y, vz = f23.x, vw = f23.y;
    float s  = vx + vy + vz + vw;
    float ss = vx * vx + vy * vy + vz * vz + vw * vw;
    #pragma unroll
    for (int o = 16; o; o >>= 1) {
        s  += __shfl_xor_sync(0xffffffffu, s,  o);
        ss += __shfl_xor_sync(0xffffffffu, ss, o);
    }
    __shared__ float sh_s[8], sh_ss[8];
    int w = t >> 5, l = t & 31;
    if (l == 0) { sh_s[w] = s; sh_ss[w] = ss; }
    __syncthreads();
    if (w == 0) {
        float a  = (l < 8) ? sh_s[l]  : 0.0f;
        float bq = (l < 8) ? sh_ss[l] : 0.0f;
        #pragma unroll
        for (int o = 4; o; o >>= 1) {
            a  += __shfl_xor_sync(0xffffffffu, a,  o);
            bq += __shfl_xor_sync(0xffffffffu, bq, o);
        }
        if (l == 0) { sh_s[0] = a; sh_ss[0] = bq; }
    }
    __syncthreads();
    float mu  = sh_s[0] * (1.0f / DMODEL);
    float var = sh_ss[0] * (1.0f / DMODEL) - mu * mu;
    float inv = rsqrtf(var + 1e-5f);
    const float4 gg = ((const float4*)G)[t];
    const float4 bb = ((const float4*)Bb)[t];
    float o0 = (vx - mu) * inv * gg.x + bb.x;
    float o1 = (vy - mu) * inv * gg.y + bb.y;
    float o2 = (vz - mu) * inv * gg.z + bb.z;
    float o3 = (vw - mu) * inv * gg.w + bb.w;
    __half* yr = Y + row * (size_t)DMODEL + t * 4;
    *(__half2*)(yr)     = __halves2half2(__float2half(o0), __float2half(o1));
    *(__half2*)(yr + 2) = __halves2half2(__float2half(o2), __float2half(o3));
}

// ---------------- per-token differential attention (fp16 in, fp16 out) -------
__global__ __launch_bounds__(64) void attn_kernel(const __half* __restrict__ QKV,
                                                  __half* __restrict__ O) {
    __shared__ float s_q[2][32][33];
    __shared__ float s_k[2][32][32];
    __shared__ float s_v[2][16][64];
    const int warp = threadIdx.x >> 5;
    const int lane = threadIdx.x & 31;
    const size_t t = (size_t)blockIdx.x * 2 + warp;
    const __half* q = QKV + t * QKVN;
    const __half* k = q + DMODEL;
    const __half* v = k + DMODEL;
    float (*qs)[33] = s_q[warp];
    float (*ks)[32] = s_k[warp];
    float (*vs)[64] = s_v[warp];

    for (int idx = lane * 2; idx < DMODEL; idx += 64) {
        int h = idx >> 6, r = idx & 63;
        int dd = r >> 1;
        float2 qv = __half22float2(*(const __half2*)(q + idx));
        float2 kv = __half22float2(*(const __half2*)(k + idx));
        float2 vv = __half22float2(*(const __half2*)(v + idx));
        qs[h][dd]      = qv.x * QSCALE;
        qs[16 + h][dd] = qv.y * QSCALE;
        ks[h][dd]      = kv.x;
        ks[16 + h][dd] = kv.y;
        ((float*)vs)[idx]     = vv.x;
        ((float*)vs)[idx + 1] = vv.y;
    }
    __syncwarp();
    float qr[32];
    #pragma unroll
    for (int d = 0; d < 32; d++) qr[d] = qs[lane][d];
    float p[32];
    #pragma unroll
    for (int j = 0; j < 32; j++) {
        float s = 0.0f;
        #pragma unroll
        for (int d = 0; d < 32; d++) s += qr[d] * ks[j][d];
        p[j] = s;
    }
    float mx = p[0];
    #pragma unroll
    for (int j = 1; j < 32; j++) mx = fmaxf(mx, p[j]);
    float sum = 0.0f;
    #pragma unroll
    for (int j = 0; j < 32; j++) { p[j] = expf(p[j] - mx); sum += p[j]; }
    float rinv = 1.0f / sum;
    __syncwarp();
    #pragma unroll
    for (int j = 0; j < 32; j++) qs[lane][j] = p[j] * rinv;
    __syncwarp();

    const float lam = g_lambda;
    const int a = lane & 15;
    const int half = lane >> 4;
    float accv[32];
    #pragma unroll
    for (int e = 0; e < 32; e++) accv[e] = 0.0f;
    #pragma unroll
    for (int h = 0; h < 16; h++) {
        float w = qs[a][h] - lam * qs[16 + a][16 + h];
        const float* vrow = &vs[h][half * 32];
        #pragma unroll
        for (int e = 0; e < 32; e++) accv[e] += w * vrow[e];
    }
    float ss = 0.0f;
    #pragma unroll
    for (int e = 0; e < 32; e++) ss += accv[e] * accv[e];
    ss += __shfl_xor_sync(0xffffffffu, ss, 16);
    float scale = rsqrtf(ss * (1.0f / 64.0f) + 1e-5f) * ONE_MINUS_LAMBDA_F;

    __half* o = O + t * (size_t)DMODEL + a * 64 + half * 32;
    #pragma unroll
    for (int e = 0; e < 32; e += 2) {
        *(__half2*)(o + e) = __halves2half2(__float2half(accv[e] * scale),
                                            __float2half(accv[e + 1] * scale));
    }
}

// ---------------- HMMA GEMM: 64x64 warp tile, BK=64, full-pitch swizzle ------
// A:[M,Ko] fp16, W:[N,Ko] fp16. acc += A*W^T.
// 128x128 CTA tile, 4 warps (2m x 2n), BK=64: each 128B-pitch smem row holds
// the full 64-k slice; chunk slot = (seg ^ (row&7)) — conflict-free stores
// and ldmatrix; ks-step is addr ^ (ks<<5), ks in 0..3.
// 3-stage ring (96 KB -> 2 CTAs/SM), one __syncthreads per 64-k iteration.
// EPI: 1=bias 2=relu 4=+res(fp32) 8=fp16 out (else fp32 out) 16=+res(fp16)
#define TILE   16384u             // 128 * 128
#define OFF_A  0u
#define OFF_W  16384u
#define STG    32768u             // per stage
#define GSMEM  98304              // 3 stages

template <int EPI>
__global__ __launch_bounds__(128, 2)
void mma_gemm(const __half* __restrict__ A, const __half* __restrict__ W,
              const float* __restrict__ bias, const float* __restrict__ res,
              const __half* __restrict__ resh,
              float* __restrict__ C, __half* __restrict__ Chl, int Nn, int Ko) {
    extern __shared__ __align__(1024) char smem[];
    const uint32_t sb = smem_u32(smem);
    const int tid = threadIdx.x;
    const int wid = tid >> 5, lane = tid & 31;
    const int m0 = blockIdx.y * 128, n0 = blockIdx.x * 128;
    const int wm = wid & 1, wn = wid >> 1;
    const int nk = Ko >> 6;            // BK = 64

    const __half* srcA = A + (size_t)m0 * Ko;
    const __half* srcW = W + (size_t)n0 * Ko;

    // cp.async mapping: 128 thr -> 16 rows x 8 segs (16B); 8 row-iters/tile
    const int ldrow0 = tid >> 3;          // 0..15
    const int ldseg  = tid & 7;           // 0..7

    // ldmatrix per-lane swizzled offsets (ks toggles via XOR ks<<5)
    const int lr = lane & 7, grp = lane >> 3;
    uint32_t aOff[4], bOff[4];
    #pragma unroll
    for (int mi = 0; mi < 4; mi++) {
        int r = wm * 64 + mi * 16 + lr + (grp & 1) * 8;
        int c = grp >> 1;
        aOff[mi] = (uint32_t)(r * 128 + ((c ^ (r & 7)) * 16));
    }
    #pragma unroll
    for (int nj = 0; nj < 4; nj++) {
        int r = wn * 64 + nj * 16 + lr + (grp >> 1) * 8;
        int c = grp & 1;
        bOff[nj] = (uint32_t)(r * 128 + ((c ^ (r & 7)) * 16));
    }

    float acc[4][8][4];
    #pragma unroll
    for (int i = 0; i < 4; i++)
        #pragma unroll
        for (int j = 0; j < 8; j++)
            #pragma unroll
            for (int e = 0; e < 4; e++) acc[i][j][e] = 0.0f;

    auto load_stage = [&](int kt, int buf) {
        uint32_t base = sb + (uint32_t)buf * STG;
        const __half* ap = srcA + kt * 64;
        const __half* wp = srcW + kt * 64;
        #pragma unroll
        for (int i = 0; i < 8; i++) {
            int row = ldrow0 + i * 16;
            uint32_t off = (uint32_t)(row * 128 + ((ldseg ^ (row & 7)) * 16));
            size_t roff = (size_t)row * Ko + ldseg * 8;
            cpasync16(base + OFF_A + off, ap + roff);
            cpasync16(base + OFF_W + off, wp + roff);
        }
        CP_COMMIT();
    };

    load_stage(0, 0);
    load_stage(1, 1);
    for (int kt = 0; kt < nk; kt++) {
        int buf = kt % 3;
        if (kt + 1 < nk) { CP_WAIT1(); } else { CP_WAIT0(); }
        __syncthreads();
        if (kt + 2 < nk) load_stage(kt + 2, (kt + 2) % 3);
        uint32_t base = sb + (uint32_t)buf * STG;
        #pragma unroll
        for (int ks = 0; ks < 4; ks++) {
            const uint32_t kx = (uint32_t)ks << 5;
            uint32_t af[4][4];
            #pragma unroll
            for (int mi = 0; mi < 4; mi++)
                LDMX4(af[mi], base + OFF_A + (aOff[mi] ^ kx));
            uint32_t bf[8][2];
            #pragma unroll
            for (int nj = 0; nj < 4; nj++) {
                uint32_t th[4];
                LDMX4(th, base + OFF_W + (bOff[nj] ^ kx));
                bf[2 * nj][0] = th[0];     bf[2 * nj][1] = th[1];
                bf[2 * nj + 1][0] = th[2]; bf[2 * nj + 1][1] = th[3];
            }
            #pragma unroll
            for (int mi = 0; mi < 4; mi++)
                #pragma unroll
                for (int ni = 0; ni < 8; ni++)
                    mma16816(acc[mi][ni][0], acc[mi][ni][1], acc[mi][ni][2], acc[mi][ni][3],
                             af[mi][0], af[mi][1], af[mi][2], af[mi][3],
                             bf[ni][0], bf[ni][1]);
        }
    }

    // epilogue
    const int gm = m0 + wm * 64;
    const int gn = n0 + wn * 64;
    const int rr = lane >> 2;
    const int cc = (lane & 3) * 2;
    #pragma unroll
    for (int mi = 0; mi < 4; mi++) {
        #pragma unroll
        for (int ni = 0; ni < 8; ni++) {
            int col = gn + ni * 8 + cc;
            float2 bv = make_float2(0.f, 0.f);
            if (EPI & 1) bv = *(const float2*)(bias + col);
            #pragma unroll
            for (int hh = 0; hh < 2; hh++) {
                int row = gm + mi * 16 + rr + hh * 8;
                float v0 = acc[mi][ni][2 * hh];
                float v1 = acc[mi][ni][2 * hh + 1];
                if (EPI & 1) { v0 += bv.x; v1 += bv.y; }
                if (EPI & 2) { v0 = fmaxf(v0, 0.0f); v1 = fmaxf(v1, 0.0f); }
                if (EPI & 4) {
                    float2 r2 = *(const float2*)(res + (size_t)row * Nn + col);
                    v0 += r2.x; v1 += r2.y;
                }
                if (EPI & 16) {
                    float2 r2 = __half22float2(*(const __half2*)(resh + (size_t)row * Nn + col));
                    v0 += r2.x; v1 += r2.y;
                }
                if (EPI & 8) {
                    *(__half2*)(Chl + (size_t)row * Nn + col) =
                        __halves2half2(__float2half(v0), __float2half(v1));
                } else {
                    *(float2*)(C + (size_t)row * Nn + col) = make_float2(v0, v1);
                }
            }
        }
    }
}

// ---------------- launch ----------------
extern "C" void kernel_launch(void* const* d_in, const int* in_sizes, int n_in,
                              void* d_out, int out_size) {
    const float* x    = (const float*)d_in[0];
    const float* Wq   = (const float*)d_in[1];
    const float* Wk   = (const float*)d_in[2];
    const float* Wv   = (const float*)d_in[3];
    const float* lq1  = (const float*)d_in[4];
    const float* lq2  = (const float*)d_in[5];
    const float* lk1  = (const float*)d_in[6];
    const float* lk2  = (const float*)d_in[7];
    const float* Wo   = (const float*)d_in[8];
    const float* bo   = (const float*)d_in[9];
    const float* ln1g = (const float*)d_in[10];
    const float* ln1b = (const float*)d_in[11];
    const float* ln2g = (const float*)d_in[12];
    const float* ln2b = (const float*)d_in[13];
    const float* W1   = (const float*)d_in[14];
    const float* b1   = (const float*)d_in[15];
    const float* W2   = (const float*)d_in[16];
    const float* b2   = (const float*)d_in[17];
    float* out = (float*)d_out;

    __half *phbf, *pqkv, *pattnbf, *pconnh, *ph2bf, *pffnbf, *pwqkv, *pwo, *pw1, *pw2;
    cudaGetSymbolAddress((void**)&phbf,    g_hbf);
    cudaGetSymbolAddress((void**)&pqkv,    g_qkv);
    cudaGetSymbolAddress((void**)&pattnbf, g_attnbf);
    cudaGetSymbolAddress((void**)&pconnh,  g_connh);
    cudaGetSymbolAddress((void**)&ph2bf,   g_h2bf);
    cudaGetSymbolAddress((void**)&pffnbf,  g_ffnbf);
    cudaGetSymbolAddress((void**)&pwqkv,   g_wqkv);
    cudaGetSymbolAddress((void**)&pwo,     g_wo);
    cudaGetSymbolAddress((void**)&pw1,     g_w1);
    cudaGetSymbolAddress((void**)&pw2,     g_w2);

    cudaFuncSetAttribute(mma_gemm<8>,  cudaFuncAttributeMaxDynamicSharedMemorySize, GSMEM);
    cudaFuncSetAttribute(mma_gemm<13>, cudaFuncAttributeMaxDynamicSharedMemorySize, GSMEM);
    cudaFuncSetAttribute(mma_gemm<11>, cudaFuncAttributeMaxDynamicSharedMemorySize, GSMEM);
    cudaFuncSetAttribute(mma_gemm<17>, cudaFuncAttributeMaxDynamicSharedMemorySize, GSMEM);

    lambda_kernel<<<1, 32>>>(lq1, lq2, lk1, lk2);

    // fused weight convert (12M elements)
    convert_all<<<(12 * WSEG) / 256, 256>>>(Wq, Wk, Wv, Wo, W1, W2,
                                            pwqkv, pwo, pw1, pw2);

    // LN1: x (fp32) -> hbf (fp16)
    ln_kernel<<<Mrows, 256>>>(x, ln1g, ln1b, phbf);

    // fused QKV: [M,1024] x [3072,1024]^T -> [M,3072] fp16
    dim3 gqkv(QKVN / 128, Mrows / 128);   // (24,128)
    mma_gemm<8><<<gqkv, 128, GSMEM>>>(phbf, pwqkv, nullptr, nullptr, nullptr,
                                      nullptr, pqkv, QKVN, DMODEL);

    attn_kernel<<<Mrows / 2, 64>>>(pqkv, pattnbf);

    // conn = x + attn @ Wo^T + bo  -> fp16
    dim3 gq(DMODEL / 128, Mrows / 128);   // (8,128)
    mma_gemm<13><<<gq, 128, GSMEM>>>(pattnbf, pwo, bo, x, nullptr,
                                     nullptr, pconnh, DMODEL, DMODEL);

    // LN2: conn (fp16) -> h2bf (fp16)
    ln_kernel_h<<<Mrows, 256>>>(pconnh, ln2g, ln2b, ph2bf);

    // ffn = relu(h2 @ W1^T + b1) -> fp16
    dim3 g1(FFDIM / 128, Mrows / 128);    // (32,128)
    mma_gemm<11><<<g1, 128, GSMEM>>>(ph2bf, pw1, b1, nullptr, nullptr,
                                     nullptr, pffnbf, FFDIM, DMODEL);

    // out = conn (fp16 res) + ffn @ W2^T + b2 -> fp32
    mma_gemm<17><<<gq, 128, GSMEM>>>(pffnbf, pw2, b2, nullptr, pconnh,
                                     out, nullptr, DMODEL, FFDIM);
}